// round 8
// baseline (speedup 1.0000x reference)
#include <cuda_runtime.h>

typedef unsigned long long ull;

#define Bsz 64
#define Ssz 512
#define Dsz 256
#define Hsz 512
#define ROWS (Bsz * Ssz)   /* 32768 */
#define GXN  (4 * Hsz)     /* 2048  */
#define NBLK 128           /* persistent CTAs (all resident on 148 SMs) */

// ---------------------------------------------------------------------------
// Static device scratch
// ---------------------------------------------------------------------------
__device__ float g_gxq[(size_t)ROWS * GXN];   // [b*512+t][j*4+gate]
__device__ float g_hs[(size_t)ROWS * Hsz];    // [b*512+t][j]
__device__ float g_hbuf[2][Bsz * Hsz];        // double-buffered h (rows: chainA 0-31, chainB 32-63)
__device__ float g_c[Bsz * Hsz];
__device__ float g_Wq[Dsz * GXN];             // packed W: [d][j*4+gate]
__device__ float g_bq[GXN];
// U packed for recurrence: ull k-pairs (U_g[2p][j], U_g[2p+1][j])
// layout: [jg(128)][p(256)][jl(4)][g(4)]  (ull)  -> 32KB per jg
__device__ ull g_Uq[128 * 256 * 4 * 4];
// per-chain flat barrier state (separate 128B lines)
__device__ unsigned g_cntA[32];
__device__ unsigned g_genA[32];
__device__ unsigned g_cntB[32];
__device__ unsigned g_genB[32];

// ---------------------------------------------------------------------------
// f32x2 + sync helpers
// ---------------------------------------------------------------------------
__device__ __forceinline__ ull fma2(ull a, ull b, ull c) {
    ull d; asm("fma.rn.f32x2 %0, %1, %2, %3;" : "=l"(d) : "l"(a), "l"(b), "l"(c)); return d;
}
__device__ __forceinline__ ull fadd2(ull a, ull b) {
    ull d; asm("add.rn.f32x2 %0, %1, %2;" : "=l"(d) : "l"(a), "l"(b)); return d;
}
__device__ __forceinline__ ull dup2(float x) {
    ull d; asm("mov.b64 %0, {%1, %1};" : "=l"(d) : "f"(x)); return d;
}
__device__ __forceinline__ ull pk2(float lo, float hi) {
    ull d; asm("mov.b64 %0, {%1, %2};" : "=l"(d) : "f"(lo), "f"(hi)); return d;
}
__device__ __forceinline__ float2 upk(ull a) {
    float2 r; asm("mov.b64 {%0, %1}, %2;" : "=f"(r.x), "=f"(r.y) : "l"(a)); return r;
}
__device__ __forceinline__ unsigned ld_acq(const unsigned* p) {
    unsigned v; asm volatile("ld.acquire.gpu.b32 %0, [%1];" : "=r"(v) : "l"(p)); return v;
}

__device__ __forceinline__ float sigmoidf_(float x) { return 1.0f / (1.0f + __expf(-x)); }
__device__ __forceinline__ float tanhf_(float x)    { return 1.0f - 2.0f / (__expf(2.0f * x) + 1.0f); }

// ---------------------------------------------------------------------------
__global__ void init_kernel() {
    int i = blockIdx.x * blockDim.x + threadIdx.x;
    g_hbuf[0][i] = 0.0f;
    if (i == 0) { g_cntA[0] = 0u; g_genA[0] = 0u; g_cntB[0] = 0u; g_genB[0] = 0u; }
}

// pack W gates interleaved (f,i,o,c) per (d,j), and biases
__global__ void pack_kernel(const float* __restrict__ Wf, const float* __restrict__ Wi,
                            const float* __restrict__ Wo, const float* __restrict__ Wc,
                            const float* __restrict__ bf, const float* __restrict__ bi,
                            const float* __restrict__ bo, const float* __restrict__ bc) {
    int idx = blockIdx.x * blockDim.x + threadIdx.x;  // Dsz*Hsz
    int d = idx >> 9;
    int j = idx & 511;
    float4 w;
    w.x = Wf[d * Hsz + j]; w.y = Wi[d * Hsz + j];
    w.z = Wo[d * Hsz + j]; w.w = Wc[d * Hsz + j];
    *(float4*)&g_Wq[(size_t)d * GXN + j * 4] = w;
    if (d == 0) {
        float4 b;
        b.x = bf[j]; b.y = bi[j]; b.z = bo[j]; b.w = bc[j];
        *(float4*)&g_bq[j * 4] = b;
    }
}

// pack U into k-pair ull layout [jg(128)][p(256)][jl(4)][g(4)]
__global__ void packu_kernel(const float* __restrict__ Uf, const float* __restrict__ Ui,
                             const float* __restrict__ Uo, const float* __restrict__ Uc) {
    int idx = blockIdx.x * blockDim.x + threadIdx.x;  // 524288
    int p = idx >> 11;                                 // 0..255
    int rem = idx & 2047;
    int j = rem >> 2;                                  // 0..511
    int g = rem & 3;
    const float* Ug = (g == 0) ? Uf : (g == 1) ? Ui : (g == 2) ? Uo : Uc;
    float lo = Ug[(size_t)(2 * p) * Hsz + j];
    float hi = Ug[(size_t)(2 * p + 1) * Hsz + j];
    int jg = j >> 2, jl = j & 3;
    g_Uq[(((size_t)jg * 256 + p) * 4 + jl) * 4 + g] = pk2(lo, hi);
}

// ---------------------------------------------------------------------------
// input-projection GEMM (R5 version — measured best, 746us)
// ---------------------------------------------------------------------------
__global__ void __launch_bounds__(256, 2)
gemm_kernel(const float* __restrict__ A) {
    __shared__ float sA[128 * 20];
    __shared__ float sB[16 * 128];

    const int tid = threadIdx.x;
    const int tx = tid & 15;
    const int ty = tid >> 4;
    const int r0 = blockIdx.y * 128;
    const int n0 = blockIdx.x * 128;

    ull acc[8][4];
    #pragma unroll
    for (int i = 0; i < 8; i++)
        #pragma unroll
        for (int p = 0; p < 4; p++) acc[i][p] = 0ull;

    for (int k0 = 0; k0 < Dsz; k0 += 16) {
        #pragma unroll
        for (int r = 0; r < 2; r++) {
            int v = r * 256 + tid;
            int mq = v >> 2, kq = v & 3;
            float4 f = *(const float4*)&A[(size_t)(r0 + mq) * Dsz + k0 + kq * 4];
            *(float4*)&sA[mq * 20 + kq * 4] = f;
        }
        #pragma unroll
        for (int r = 0; r < 2; r++) {
            int v = r * 256 + tid;
            int kk = v >> 5, nq = v & 31;
            float4 f = *(const float4*)&g_Wq[(size_t)(k0 + kk) * GXN + n0 + nq * 4];
            *(float4*)&sB[kk * 128 + nq * 4] = f;
        }
        __syncthreads();

        #pragma unroll
        for (int kk = 0; kk < 16; kk++) {
            float av[8];
            #pragma unroll
            for (int i = 0; i < 8; i++) av[i] = sA[(ty * 8 + i) * 20 + kk];
            ulonglong2 b0 = *(const ulonglong2*)&sB[kk * 128 + tx * 8];
            ulonglong2 b1 = *(const ulonglong2*)&sB[kk * 128 + tx * 8 + 4];
            #pragma unroll
            for (int i = 0; i < 8; i++) {
                ull a2 = dup2(av[i]);
                acc[i][0] = fma2(b0.x, a2, acc[i][0]);
                acc[i][1] = fma2(b0.y, a2, acc[i][1]);
                acc[i][2] = fma2(b1.x, a2, acc[i][2]);
                acc[i][3] = fma2(b1.y, a2, acc[i][3]);
            }
        }
        __syncthreads();
    }

    ulonglong2 bA = *(const ulonglong2*)&g_bq[n0 + tx * 8];
    ulonglong2 bB = *(const ulonglong2*)&g_bq[n0 + tx * 8 + 4];
    #pragma unroll
    for (int i = 0; i < 8; i++) {
        acc[i][0] = fadd2(acc[i][0], bA.x);
        acc[i][1] = fadd2(acc[i][1], bA.y);
        acc[i][2] = fadd2(acc[i][2], bB.x);
        acc[i][3] = fadd2(acc[i][3], bB.y);
        float* dst = &g_gxq[(size_t)(r0 + ty * 8 + i) * GXN + n0 + tx * 8];
        ulonglong2 s0; s0.x = acc[i][0]; s0.y = acc[i][1];
        ulonglong2 s1; s1.x = acc[i][2]; s1.y = acc[i][3];
        *(ulonglong2*)dst = s0;
        *(ulonglong2*)(dst + 4) = s1;
    }
}

// ---------------------------------------------------------------------------
// persistent LSTM recurrence — DUAL-CHAIN INTERLEAVED
//   Two independent recurrence chains: A = samples 0-31, B = samples 32-63.
//   All 128 CTAs serve BOTH chains: each CTA owns 4 j-columns (jg=blockIdx.x).
//   Per iteration: [waitA, stageA, computeA, arriveA] [waitB, stageB,
//   computeB, arriveB] — each chain's barrier latency hides behind the other
//   chain's compute.
//   thread: jl = tid&3, bp = (tid>>2)&31, ks = tid>>7 (4-way k split, 1 cell)
//   SMEM: sU  256p x 128B (4jl x 4g ull, conflict-free) = 32 KB
//         sH  32 b-rows x 516 floats (padded)           = 66 KB
//         sRed 3 x 128 cells x float4                   = 6 KB
// ---------------------------------------------------------------------------
#define SU_BYTES  (256 * 128)                  /* 32768 */
#define SH_OFF    SU_BYTES
#define SH_STRIDE 516
#define SH_BYTES  (32 * SH_STRIDE * 4)         /* 66048 */
#define SRED_OFF  (SH_OFF + SH_BYTES)          /* 98816 */
#define SRED_BYTES (3 * 128 * 16)              /* 6144 */
#define RECUR_SMEM (SRED_OFF + SRED_BYTES)     /* 104960 */

struct ChainState { float c; };

__global__ void __launch_bounds__(512, 1)
recur_kernel() {
    extern __shared__ char smem[];
    char*   sU   = smem;
    float*  sH   = (float*)(smem + SH_OFF);
    float4* sRed = (float4*)(smem + SRED_OFF);

    const int tid = threadIdx.x;
    const int jl  = tid & 3;
    const int bp  = (tid >> 2) & 31;
    const int ks  = tid >> 7;
    const int jg  = blockIdx.x;
    const int j   = jg * 4 + jl;
    const int cell = bp * 4 + jl;              // 0..127

    // ---- load U slice (32KB) into conflict-free SMEM (once) ----
    {
        const ull* uq = &g_Uq[(size_t)jg * 4096];
        #pragma unroll
        for (int r = 0; r < 8; r++) {
            int v = r * 512 + tid;             // 0..4095 ull
            ((ull*)sU)[v] = uq[v];             // same linear layout: [p][jl][g]
        }
    }

    const char* uBase = sU + jl * 32 + ks * 64 * 128;  // ks window: 64 p-pairs
    float cA = 0.0f, cB = 0.0f;

    for (int t = 0; t < Ssz; t++) {
        const int   rd = t & 1;
        const int   wr = rd ^ 1;
        const unsigned stp = (unsigned)t;       // wait target for this step

        // gx prefetch for both chains (ks==0 threads = tid<128)
        float4 gxA, gxB;
        if (ks == 0) {
            gxA = *(const float4*)&g_gxq[(size_t)(bp * Ssz + t) * GXN + j * 4];
            gxB = *(const float4*)&g_gxq[(size_t)((bp + 32) * Ssz + t) * GXN + j * 4];
        }

        #pragma unroll
        for (int chain = 0; chain < 2; chain++) {
            const int  bbase = chain * 32;
            unsigned*  cnt   = chain ? g_cntB : g_cntA;
            unsigned*  gen   = chain ? g_genB : g_genA;
            const float4 gx  = chain ? gxB : gxA;
            float&     cst   = chain ? cB : cA;

            // ---- wait for this chain's h(t) (skipped at t=0) ----
            if (t > 0) {
                if (tid == 0) {
                    long long spins = 0;
                    while (ld_acq(gen) < stp) {
                        __nanosleep(64);
                        if (++spins > 50000000LL) break;   // anti-wedge
                    }
                }
                __syncthreads();
            }

            // ---- stage h(t) rows [bbase, bbase+32) into SMEM ----
            const float* hp = g_hbuf[rd];
            #pragma unroll
            for (int r = 0; r < 8; r++) {
                int v = r * 512 + tid;          // float4 index 0..4095
                int row = v >> 7, c4 = v & 127;
                float4 f = __ldcg((const float4*)&hp[(bbase + row) * Hsz + c4 * 4]);
                *(float4*)&sH[row * SH_STRIDE + c4 * 4] = f;
            }
            __syncthreads();

            // ---- compute: 1 cell, 128-k window, pair-over-k FFMA2 ----
            ull aF = 0, aI = 0, aO = 0, aC = 0;
            {
                const ulonglong2* hrow = (const ulonglong2*)&sH[bp * SH_STRIDE + ks * 128];
                const char* up = uBase;
                #pragma unroll 8
                for (int i = 0; i < 32; i++) {  // 2 p (4 k) per iter
                    ulonglong2 u0a = *(const ulonglong2*)(up);        // f,i pairs (p)
                    ulonglong2 u0b = *(const ulonglong2*)(up + 16);   // o,c pairs (p)
                    ulonglong2 u1a = *(const ulonglong2*)(up + 128);  // f,i (p+1)
                    ulonglong2 u1b = *(const ulonglong2*)(up + 144);  // o,c (p+1)
                    ulonglong2 ha  = hrow[i];                          // 4 h values
                    aF = fma2(u0a.x, ha.x, aF);  aI = fma2(u0a.y, ha.x, aI);
                    aO = fma2(u0b.x, ha.x, aO);  aC = fma2(u0b.y, ha.x, aC);
                    aF = fma2(u1a.x, ha.y, aF);  aI = fma2(u1a.y, ha.y, aI);
                    aO = fma2(u1b.x, ha.y, aO);  aC = fma2(u1b.y, ha.y, aC);
                    up += 256;
                }
            }

            // fold f32x2 lanes -> scalars
            float2 t2;
            float4 part;
            t2 = upk(aF); part.x = t2.x + t2.y;
            t2 = upk(aI); part.y = t2.x + t2.y;
            t2 = upk(aO); part.z = t2.x + t2.y;
            t2 = upk(aC); part.w = t2.x + t2.y;

            if (ks != 0) sRed[(ks - 1) * 128 + cell] = part;
            __syncthreads();

            // ---- epilogue: ks==0 reduces, gates, writes h(t+1) ----
            if (ks == 0) {
                float4 q0 = sRed[cell], q1 = sRed[128 + cell], q2 = sRed[256 + cell];
                float pf = gx.x + part.x + q0.x + q1.x + q2.x;
                float pi = gx.y + part.y + q0.y + q1.y + q2.y;
                float po = gx.z + part.z + q0.z + q1.z + q2.z;
                float pc = gx.w + part.w + q0.w + q1.w + q2.w;

                cst = sigmoidf_(pf) * cst + sigmoidf_(pi) * tanhf_(pc);
                float hn = sigmoidf_(po) * tanhf_(cst);

                int bglob = bbase + bp;
                g_hbuf[wr][bglob * Hsz + j] = hn;
                g_hs[(size_t)(bglob * Ssz + t) * Hsz + j] = hn;
            }

            // ---- arrive on this chain's barrier (NO wait here) ----
            __threadfence();
            __syncthreads();
            if (tid == 0) {
                unsigned target = (unsigned)NBLK * (unsigned)(t + 1);
                unsigned prev = atomicAdd(cnt, 1u);
                if (prev + 1u == target) atomicExch(gen, (unsigned)(t + 1));
            }
        }
    }

    if (ks == 0) {
        g_c[bp * Hsz + j]        = cA;
        g_c[(bp + 32) * Hsz + j] = cB;
    }
}

// ---------------------------------------------------------------------------
__global__ void head_kernel(const float* __restrict__ Wfc, const float* __restrict__ bfc,
                            float* __restrict__ out) {
    int warp = blockIdx.x * 8 + (threadIdx.x >> 5);
    int lane = threadIdx.x & 31;
    const float* hrow = &g_hs[(size_t)warp * Hsz];
    float acc = 0.0f;
    #pragma unroll
    for (int q = 0; q < 4; q++) {
        float4 h = *(const float4*)&hrow[q * 128 + lane * 4];
        float4 w = *(const float4*)&Wfc[q * 128 + lane * 4];
        acc += h.x * w.x + h.y * w.y + h.z * w.z + h.w * w.w;
    }
    #pragma unroll
    for (int s = 16; s > 0; s >>= 1) acc += __shfl_xor_sync(0xFFFFFFFFu, acc, s);
    if (lane == 0) out[warp] = acc + bfc[0];
}

__global__ void fin_kernel(float* __restrict__ out) {
    int i = blockIdx.x * blockDim.x + threadIdx.x;
    out[32768 + i] = g_hbuf[0][i];
    out[65536 + i] = g_c[i];
}

// ---------------------------------------------------------------------------
extern "C" void kernel_launch(void* const* d_in, const int* in_sizes, int n_in,
                              void* d_out, int out_size) {
    const float* x   = (const float*)d_in[0];
    const float* Wf  = (const float*)d_in[1];
    const float* Wi  = (const float*)d_in[2];
    const float* Wo  = (const float*)d_in[3];
    const float* Wc  = (const float*)d_in[4];
    const float* bf  = (const float*)d_in[5];
    const float* bi  = (const float*)d_in[6];
    const float* bo  = (const float*)d_in[7];
    const float* bc  = (const float*)d_in[8];
    const float* Uf  = (const float*)d_in[9];
    const float* Ui  = (const float*)d_in[10];
    const float* Uo  = (const float*)d_in[11];
    const float* Uc  = (const float*)d_in[12];
    const float* Wfc = (const float*)d_in[13];
    const float* bfc = (const float*)d_in[14];
    float* out = (float*)d_out;

    cudaFuncSetAttribute(recur_kernel, cudaFuncAttributeMaxDynamicSharedMemorySize, RECUR_SMEM);

    init_kernel<<<64, 512>>>();
    pack_kernel<<<512, 256>>>(Wf, Wi, Wo, Wc, bf, bi, bo, bc);
    packu_kernel<<<2048, 256>>>(Uf, Ui, Uo, Uc);
    gemm_kernel<<<dim3(GXN / 128, ROWS / 128), 256>>>(x);
    recur_kernel<<<NBLK, 512, RECUR_SMEM>>>();
    head_kernel<<<ROWS / 8, 256>>>(Wfc, bfc, out);
    fin_kernel<<<64, 512>>>(out);
}

// round 10
// speedup vs baseline: 1.7170x; 1.7170x over previous
#include <cuda_runtime.h>
#include <cuda_bf16.h>

typedef unsigned long long ull;

#define Bsz 64
#define Ssz 512
#define Dsz 256
#define Hsz 512
#define ROWS (Bsz * Ssz)   /* 32768 */
#define GXN  (4 * Hsz)     /* 2048  */
#define NBLK 128           /* persistent CTAs (all resident on 148 SMs) */

// ---------------------------------------------------------------------------
// Static device scratch
// ---------------------------------------------------------------------------
__device__ float g_gxq[(size_t)ROWS * GXN];   // [b*512+t][j*4+gate]
__device__ float g_hs[(size_t)ROWS * Hsz];    // [b*512+t][j]
__device__ float g_hbuf[2][Bsz * Hsz];        // double-buffered h
__device__ float g_c[Bsz * Hsz];
__device__ float g_Wq[Dsz * GXN];             // packed W: [d][j*4+gate]
__device__ float g_bq[GXN];
// U packed for recurrence: ull pairs (U_g[2p][j], U_g[2p+1][j])
// layout: [jg(64)][p(256)][j8(8)][g(4)]  (ull)
__device__ ull g_Uq[64 * 256 * 8 * 4];
__device__ unsigned g_count;
__device__ unsigned g_gen;
// bf16 split operands for the tensor-core input GEMM
__device__ __nv_bfloat16 g_xhi[(size_t)ROWS * Dsz];
__device__ __nv_bfloat16 g_xlo[(size_t)ROWS * Dsz];
__device__ __nv_bfloat16 g_Wthi[(size_t)GXN * Dsz];   // [n][k] (transposed)
__device__ __nv_bfloat16 g_Wtlo[(size_t)GXN * Dsz];

// ---------------------------------------------------------------------------
// f32x2 + sync helpers
// ---------------------------------------------------------------------------
__device__ __forceinline__ ull fma2(ull a, ull b, ull c) {
    ull d; asm("fma.rn.f32x2 %0, %1, %2, %3;" : "=l"(d) : "l"(a), "l"(b), "l"(c)); return d;
}
__device__ __forceinline__ ull pk2(float lo, float hi) {
    ull d; asm("mov.b64 %0, {%1, %2};" : "=l"(d) : "f"(lo), "f"(hi)); return d;
}
__device__ __forceinline__ float2 upk(ull a) {
    float2 r; asm("mov.b64 {%0, %1}, %2;" : "=f"(r.x), "=f"(r.y) : "l"(a)); return r;
}
__device__ __forceinline__ unsigned ld_acq(const unsigned* p) {
    unsigned v; asm volatile("ld.acquire.gpu.b32 %0, [%1];" : "=r"(v) : "l"(p)); return v;
}
__device__ __forceinline__ float sigmoidf_(float x) { return 1.0f / (1.0f + __expf(-x)); }
__device__ __forceinline__ float tanhf_(float x)    { return 1.0f - 2.0f / (__expf(2.0f * x) + 1.0f); }

__device__ __forceinline__ unsigned smem_u32(const void* p) {
    unsigned a;
    asm("{ .reg .u64 t; cvta.to.shared.u64 t, %1; cvt.u32.u64 %0, t; }" : "=r"(a) : "l"(p));
    return a;
}
// ldmatrix x4 (sm_75+ baseline PTX; no 'a' features)
__device__ __forceinline__ void ldsm4(unsigned& r0, unsigned& r1, unsigned& r2, unsigned& r3,
                                      unsigned addr) {
    asm volatile("ldmatrix.sync.aligned.m8n8.x4.shared.b16 {%0,%1,%2,%3}, [%4];"
                 : "=r"(r0), "=r"(r1), "=r"(r2), "=r"(r3) : "r"(addr));
}
// bf16 mma (sm_80+ baseline PTX)
__device__ __forceinline__ void mma_bf16(float& c0, float& c1, float& c2, float& c3,
                                         unsigned a0, unsigned a1, unsigned a2, unsigned a3,
                                         unsigned b0, unsigned b1) {
    asm volatile("mma.sync.aligned.m16n8k16.row.col.f32.bf16.bf16.f32 "
                 "{%0,%1,%2,%3}, {%4,%5,%6,%7}, {%8,%9}, {%0,%1,%2,%3};"
                 : "+f"(c0), "+f"(c1), "+f"(c2), "+f"(c3)
                 : "r"(a0), "r"(a1), "r"(a2), "r"(a3), "r"(b0), "r"(b1));
}

// ---------------------------------------------------------------------------
__global__ void init_kernel() {
    int i = blockIdx.x * blockDim.x + threadIdx.x;
    g_hbuf[0][i] = 0.0f;
    if (i == 0) { g_count = 0u; g_gen = 0u; }
}

// pack W gates interleaved (f,i,o,c) per (d,j), and biases
__global__ void pack_kernel(const float* __restrict__ Wf, const float* __restrict__ Wi,
                            const float* __restrict__ Wo, const float* __restrict__ Wc,
                            const float* __restrict__ bf, const float* __restrict__ bi,
                            const float* __restrict__ bo, const float* __restrict__ bc) {
    int idx = blockIdx.x * blockDim.x + threadIdx.x;  // Dsz*Hsz
    int d = idx >> 9;
    int j = idx & 511;
    float4 w;
    w.x = Wf[d * Hsz + j]; w.y = Wi[d * Hsz + j];
    w.z = Wo[d * Hsz + j]; w.w = Wc[d * Hsz + j];
    *(float4*)&g_Wq[(size_t)d * GXN + j * 4] = w;
    if (d == 0) {
        float4 b;
        b.x = bf[j]; b.y = bi[j]; b.z = bo[j]; b.w = bc[j];
        *(float4*)&g_bq[j * 4] = b;
    }
}

// pack U into k-pair ull layout [jg][p][j8][g]
__global__ void packu_kernel(const float* __restrict__ Uf, const float* __restrict__ Ui,
                             const float* __restrict__ Uo, const float* __restrict__ Uc) {
    int idx = blockIdx.x * blockDim.x + threadIdx.x;  // 524288
    int p = idx >> 11;
    int rem = idx & 2047;
    int j = rem >> 2;
    int g = rem & 3;
    const float* Ug = (g == 0) ? Uf : (g == 1) ? Ui : (g == 2) ? Uo : Uc;
    float lo = Ug[(size_t)(2 * p) * Hsz + j];
    float hi = Ug[(size_t)(2 * p + 1) * Hsz + j];
    int jg = j >> 3, j8 = j & 7;
    g_Uq[(((size_t)jg * 256 + p) * 8 + j8) * 4 + g] = pk2(lo, hi);
}

// split x into bf16 hi/lo
__global__ void splitx_kernel(const float* __restrict__ x) {
    size_t i = (size_t)blockIdx.x * blockDim.x + threadIdx.x;   // ROWS*Dsz
    float v = x[i];
    __nv_bfloat16 hi = __float2bfloat16(v);
    g_xhi[i] = hi;
    g_xlo[i] = __float2bfloat16(v - __bfloat162float(hi));
}

// build transposed bf16 hi/lo W: Wt[n][k] = Wq[k][n]  (needs pack_kernel first)
__global__ void packwt_kernel() {
    int idx = blockIdx.x * blockDim.x + threadIdx.x;   // GXN*Dsz = 524288
    int n = idx >> 8;
    int k = idx & 255;
    float v = g_Wq[(size_t)k * GXN + n];
    __nv_bfloat16 hi = __float2bfloat16(v);
    g_Wthi[(size_t)n * Dsz + k] = hi;
    g_Wtlo[(size_t)n * Dsz + k] = __float2bfloat16(v - __bfloat162float(hi));
}

// ---------------------------------------------------------------------------
// mma.sync bf16 split-precision input GEMM
//   gx[m][n] = sum_k x[m][k]*W[k][n] + b[n],  M=32768, N=2048, K=256
//   CTA 256thr = 8 warps (4m x 2n); tile 128m x 64n; warp tile 32x32.
//   B resident in SMEM (stride 264 bf16 -> conflict-free ldmatrix);
//   A streamed in k=32 chunks (stride 40). 3 products hi*hi+hi*lo+lo*hi.
// ---------------------------------------------------------------------------
#define SB_ST   264                         /* bf16 units per B row */
#define SA_ST   40                          /* bf16 units per A row */
#define SB_HI   0
#define SB_LO   (64 * SB_ST * 2)            /* 33792 */
#define SA_HI   (2 * 64 * SB_ST * 2)        /* 67584 */
#define SA_LO   (SA_HI + 128 * SA_ST * 2)   /* 77824 */
#define GT_SMEM (SA_LO + 128 * SA_ST * 2)   /* 88064 */

__global__ void __launch_bounds__(256, 2)
gemm_tc_kernel() {
    extern __shared__ char smem[];
    const unsigned sbase = smem_u32(smem);

    const int tid  = threadIdx.x;
    const int lane = tid & 31;
    const int wid  = tid >> 5;
    const int wm   = wid & 3;               // warp m index (0..3)
    const int wn   = wid >> 2;              // warp n index (0..1)
    const int m0w  = wm * 32;
    const int n0w  = wn * 32;
    const int n0   = blockIdx.x * 64;
    const int r0   = blockIdx.y * 128;

    // ---- load full B tile (64 x 256 bf16, hi+lo) into SMEM ----
    #pragma unroll
    for (int r = 0; r < 8; r++) {
        int v = r * 256 + tid;              // 0..2047 uint4
        int row = v >> 5, cu = v & 31;
        size_t src = (size_t)(n0 + row) * Dsz + cu * 8;
        *(uint4*)(smem + SB_HI + (row * SB_ST + cu * 8) * 2) = *(const uint4*)&g_Wthi[src];
        *(uint4*)(smem + SB_LO + (row * SB_ST + cu * 8) * 2) = *(const uint4*)&g_Wtlo[src];
    }

    float c[2][4][4];
    #pragma unroll
    for (int mi = 0; mi < 2; mi++)
        #pragma unroll
        for (int ni = 0; ni < 4; ni++)
            #pragma unroll
            for (int e = 0; e < 4; e++) c[mi][ni][e] = 0.0f;

    // ldmatrix lane address components
    const int aRow  = lane & 15;            // A: row within 16-row frag
    const int aKoff = (lane >> 4) * 8;      // A: k offset 0/8
    const int bSel  = lane >> 3;            // B: matrix select 0..3
    const int bRow  = (bSel >> 1) * 8 + (lane & 7);
    const int bKoff = (bSel & 1) * 8;

    for (int kc = 0; kc < 8; kc++) {
        // ---- stage A chunk (128 x 32 bf16, hi+lo) ----
        __syncthreads();
        #pragma unroll
        for (int r = 0; r < 2; r++) {
            int v = r * 256 + tid;          // 0..511 uint4
            int row = v >> 2, cu = v & 3;
            size_t src = (size_t)(r0 + row) * Dsz + kc * 32 + cu * 8;
            *(uint4*)(smem + SA_HI + (row * SA_ST + cu * 8) * 2) = *(const uint4*)&g_xhi[src];
            *(uint4*)(smem + SA_LO + (row * SA_ST + cu * 8) * 2) = *(const uint4*)&g_xlo[src];
        }
        __syncthreads();

        #pragma unroll
        for (int ks = 0; ks < 2; ks++) {
            const int kchunk = ks * 16;             // k offset within A chunk
            const int kglob  = kc * 32 + kchunk;    // k offset within B tile

            // A fragments (hi/lo) for 2 m-frags
            unsigned ah[2][4], al[2][4];
            #pragma unroll
            for (int mi = 0; mi < 2; mi++) {
                unsigned off = (unsigned)((m0w + mi * 16 + aRow) * SA_ST + kchunk + aKoff) * 2;
                ldsm4(ah[mi][0], ah[mi][1], ah[mi][2], ah[mi][3], sbase + SA_HI + off);
                ldsm4(al[mi][0], al[mi][1], al[mi][2], al[mi][3], sbase + SA_LO + off);
            }
            // B fragments (hi/lo) for 4 n-frags (two x4 each)
            unsigned bh[4][2], bl[4][2];
            #pragma unroll
            for (int half = 0; half < 2; half++) {
                unsigned off = (unsigned)((n0w + half * 16 + bRow) * SB_ST + kglob + bKoff) * 2;
                ldsm4(bh[half * 2][0], bh[half * 2][1], bh[half * 2 + 1][0], bh[half * 2 + 1][1],
                      sbase + SB_HI + off);
                ldsm4(bl[half * 2][0], bl[half * 2][1], bl[half * 2 + 1][0], bl[half * 2 + 1][1],
                      sbase + SB_LO + off);
            }

            #pragma unroll
            for (int mi = 0; mi < 2; mi++)
                #pragma unroll
                for (int ni = 0; ni < 4; ni++) {
                    float* cc = c[mi][ni];
                    mma_bf16(cc[0], cc[1], cc[2], cc[3],
                             ah[mi][0], ah[mi][1], ah[mi][2], ah[mi][3],
                             bh[ni][0], bh[ni][1]);
                    mma_bf16(cc[0], cc[1], cc[2], cc[3],
                             ah[mi][0], ah[mi][1], ah[mi][2], ah[mi][3],
                             bl[ni][0], bl[ni][1]);
                    mma_bf16(cc[0], cc[1], cc[2], cc[3],
                             al[mi][0], al[mi][1], al[mi][2], al[mi][3],
                             bh[ni][0], bh[ni][1]);
                }
        }
    }

    // ---- epilogue: bias + store ----
    const int crow = lane >> 2;
    const int ccol = (lane & 3) * 2;
    #pragma unroll
    for (int mi = 0; mi < 2; mi++) {
        #pragma unroll
        for (int ni = 0; ni < 4; ni++) {
            int col = n0 + n0w + ni * 8 + ccol;
            float2 bb = *(const float2*)&g_bq[col];
            int m1 = r0 + m0w + mi * 16 + crow;
            float2 o0; o0.x = c[mi][ni][0] + bb.x; o0.y = c[mi][ni][1] + bb.y;
            float2 o1; o1.x = c[mi][ni][2] + bb.x; o1.y = c[mi][ni][3] + bb.y;
            *(float2*)&g_gxq[(size_t)m1 * GXN + col] = o0;
            *(float2*)&g_gxq[(size_t)(m1 + 8) * GXN + col] = o1;
        }
    }
}

// ---------------------------------------------------------------------------
// persistent LSTM recurrence — EXACT best-measured version (4961us run)
// ---------------------------------------------------------------------------
#define SU_BYTES  (256 * 8 * 48)                 /* 98304 */
#define SH_OFF    SU_BYTES
#define SH_STRIDE 516
#define SH_BYTES  (32 * SH_STRIDE * 4)           /* 66048 */
#define SRED_OFF  (SH_OFF + SH_BYTES)            /* 164352 */
#define SRED_BYTES (3 * 256 * 16)                /* 12288 */
#define RECUR_SMEM (SRED_OFF + SRED_BYTES)       /* 176640 */

__global__ void __launch_bounds__(512, 1)
recur_kernel() {
    extern __shared__ char smem[];
    char*  sU   = smem;
    float* sH   = (float*)(smem + SH_OFF);
    float4* sRed = (float4*)(smem + SRED_OFF);

    const int tid = threadIdx.x;
    const int j8  = tid & 7;
    const int bp  = (tid >> 3) & 15;
    const int ks  = tid >> 7;
    const int jg  = blockIdx.x >> 1;
    const int bg  = blockIdx.x & 1;
    const int j   = jg * 8 + j8;
    const int b0g = bg * 32 + bp;
    const int b1g = b0g + 16;

    {
        const ull* uq = &g_Uq[(size_t)jg * 8192];
        for (int r = 0; r < 16; r++) {
            int v = r * 512 + tid;
            int p = v >> 5, jj = (v >> 2) & 7, g = v & 3;
            *(ull*)(sU + p * 384 + jj * 48 + g * 8) = uq[v];
        }
    }

    const char* uBase = sU + j8 * 48 + ks * 64 * 384;
    float c0 = 0.0f, c1 = 0.0f;

    for (int t = 0; t < Ssz; t++) {
        const float* hp = g_hbuf[t & 1];

        float4 gx0, gx1;
        if (ks == 0) {
            gx0 = *(const float4*)&g_gxq[(size_t)(b0g * Ssz + t) * GXN + j * 4];
            gx1 = *(const float4*)&g_gxq[(size_t)(b1g * Ssz + t) * GXN + j * 4];
        }

        #pragma unroll
        for (int r = 0; r < 8; r++) {
            int v = r * 512 + tid;
            int row = v >> 7, c4 = v & 127;
            float4 f = __ldcg((const float4*)&hp[(bg * 32 + row) * Hsz + c4 * 4]);
            *(float4*)&sH[row * SH_STRIDE + c4 * 4] = f;
        }
        __syncthreads();

        ull aF0 = 0, aI0 = 0, aO0 = 0, aC0 = 0;
        ull aF1 = 0, aI1 = 0, aO1 = 0, aC1 = 0;
        {
            const ulonglong2* hA = (const ulonglong2*)&sH[bp * SH_STRIDE + ks * 128];
            const ulonglong2* hB = (const ulonglong2*)&sH[(bp + 16) * SH_STRIDE + ks * 128];
            const char* up = uBase;
            #pragma unroll 8
            for (int i = 0; i < 32; i++) {
                ulonglong2 ufi0 = *(const ulonglong2*)(up);
                ulonglong2 uoc0 = *(const ulonglong2*)(up + 16);
                ulonglong2 ufi1 = *(const ulonglong2*)(up + 384);
                ulonglong2 uoc1 = *(const ulonglong2*)(up + 400);
                ulonglong2 ha = hA[i];
                ulonglong2 hb = hB[i];
                aF0 = fma2(ufi0.x, ha.x, aF0);  aI0 = fma2(ufi0.y, ha.x, aI0);
                aO0 = fma2(uoc0.x, ha.x, aO0);  aC0 = fma2(uoc0.y, ha.x, aC0);
                aF1 = fma2(ufi0.x, hb.x, aF1);  aI1 = fma2(ufi0.y, hb.x, aI1);
                aO1 = fma2(uoc0.x, hb.x, aO1);  aC1 = fma2(uoc0.y, hb.x, aC1);
                aF0 = fma2(ufi1.x, ha.y, aF0);  aI0 = fma2(ufi1.y, ha.y, aI0);
                aO0 = fma2(uoc1.x, ha.y, aO0);  aC0 = fma2(uoc1.y, ha.y, aC0);
                aF1 = fma2(ufi1.x, hb.y, aF1);  aI1 = fma2(ufi1.y, hb.y, aI1);
                aO1 = fma2(uoc1.x, hb.y, aO1);  aC1 = fma2(uoc1.y, hb.y, aC1);
                up += 768;
            }
        }

        float2 t2;
        float4 p0, p1;
        t2 = upk(aF0); p0.x = t2.x + t2.y;   t2 = upk(aI0); p0.y = t2.x + t2.y;
        t2 = upk(aO0); p0.z = t2.x + t2.y;   t2 = upk(aC0); p0.w = t2.x + t2.y;
        t2 = upk(aF1); p1.x = t2.x + t2.y;   t2 = upk(aI1); p1.y = t2.x + t2.y;
        t2 = upk(aO1); p1.z = t2.x + t2.y;   t2 = upk(aC1); p1.w = t2.x + t2.y;

        int cell0 = bp * 8 + j8;
        if (ks != 0) {
            sRed[(ks - 1) * 256 + cell0]       = p0;
            sRed[(ks - 1) * 256 + cell0 + 128] = p1;
        }
        __syncthreads();

        if (ks == 0) {
            float4 q0 = sRed[cell0],        q1 = sRed[256 + cell0],        q2 = sRed[512 + cell0];
            float4 r0_ = sRed[cell0 + 128], r1_ = sRed[256 + cell0 + 128], r2_ = sRed[512 + cell0 + 128];
            float pf0 = gx0.x + p0.x + q0.x + q1.x + q2.x;
            float pi0 = gx0.y + p0.y + q0.y + q1.y + q2.y;
            float po0 = gx0.z + p0.z + q0.z + q1.z + q2.z;
            float pc0 = gx0.w + p0.w + q0.w + q1.w + q2.w;
            float pf1 = gx1.x + p1.x + r0_.x + r1_.x + r2_.x;
            float pi1 = gx1.y + p1.y + r0_.y + r1_.y + r2_.y;
            float po1 = gx1.z + p1.z + r0_.z + r1_.z + r2_.z;
            float pc1 = gx1.w + p1.w + r0_.w + r1_.w + r2_.w;

            c0 = sigmoidf_(pf0) * c0 + sigmoidf_(pi0) * tanhf_(pc0);
            float h0 = sigmoidf_(po0) * tanhf_(c0);
            c1 = sigmoidf_(pf1) * c1 + sigmoidf_(pi1) * tanhf_(pc1);
            float h1 = sigmoidf_(po1) * tanhf_(c1);

            float* hn = g_hbuf[(t + 1) & 1];
            hn[b0g * Hsz + j] = h0;
            hn[b1g * Hsz + j] = h1;
            g_hs[(size_t)(b0g * Ssz + t) * Hsz + j] = h0;
            g_hs[(size_t)(b1g * Ssz + t) * Hsz + j] = h1;
        }

        __threadfence();
        __syncthreads();
        if (tid == 0) {
            unsigned target = (unsigned)NBLK * (unsigned)(t + 1);
            unsigned prev = atomicAdd(&g_count, 1u);
            if (prev + 1u == target) {
                atomicExch(&g_gen, (unsigned)(t + 1));
            } else {
                long long spins = 0;
                while (ld_acq(&g_gen) < (unsigned)(t + 1)) {
                    __nanosleep(64);
                    if (++spins > 100000000LL) break;
                }
            }
        }
        __syncthreads();
    }

    if (ks == 0) {
        g_c[b0g * Hsz + j] = c0;
        g_c[b1g * Hsz + j] = c1;
    }
}

// ---------------------------------------------------------------------------
__global__ void head_kernel(const float* __restrict__ Wfc, const float* __restrict__ bfc,
                            float* __restrict__ out) {
    int warp = blockIdx.x * 8 + (threadIdx.x >> 5);
    int lane = threadIdx.x & 31;
    const float* hrow = &g_hs[(size_t)warp * Hsz];
    float acc = 0.0f;
    #pragma unroll
    for (int q = 0; q < 4; q++) {
        float4 h = *(const float4*)&hrow[q * 128 + lane * 4];
        float4 w = *(const float4*)&Wfc[q * 128 + lane * 4];
        acc += h.x * w.x + h.y * w.y + h.z * w.z + h.w * w.w;
    }
    #pragma unroll
    for (int s = 16; s > 0; s >>= 1) acc += __shfl_xor_sync(0xFFFFFFFFu, acc, s);
    if (lane == 0) out[warp] = acc + bfc[0];
}

__global__ void fin_kernel(float* __restrict__ out) {
    int i = blockIdx.x * blockDim.x + threadIdx.x;
    out[32768 + i] = g_hbuf[0][i];
    out[65536 + i] = g_c[i];
}

// ---------------------------------------------------------------------------
extern "C" void kernel_launch(void* const* d_in, const int* in_sizes, int n_in,
                              void* d_out, int out_size) {
    const float* x   = (const float*)d_in[0];
    const float* Wf  = (const float*)d_in[1];
    const float* Wi  = (const float*)d_in[2];
    const float* Wo  = (const float*)d_in[3];
    const float* Wc  = (const float*)d_in[4];
    const float* bf  = (const float*)d_in[5];
    const float* bi  = (const float*)d_in[6];
    const float* bo  = (const float*)d_in[7];
    const float* bc  = (const float*)d_in[8];
    const float* Uf  = (const float*)d_in[9];
    const float* Ui  = (const float*)d_in[10];
    const float* Uo  = (const float*)d_in[11];
    const float* Uc  = (const float*)d_in[12];
    const float* Wfc = (const float*)d_in[13];
    const float* bfc = (const float*)d_in[14];
    float* out = (float*)d_out;

    cudaFuncSetAttribute(recur_kernel, cudaFuncAttributeMaxDynamicSharedMemorySize, RECUR_SMEM);
    cudaFuncSetAttribute(gemm_tc_kernel, cudaFuncAttributeMaxDynamicSharedMemorySize, GT_SMEM);

    init_kernel<<<64, 512>>>();
    pack_kernel<<<512, 256>>>(Wf, Wi, Wo, Wc, bf, bi, bo, bc);
    packu_kernel<<<2048, 256>>>(Uf, Ui, Uo, Uc);
    splitx_kernel<<<ROWS * Dsz / 256, 256>>>(x);
    packwt_kernel<<<2048, 256>>>();
    gemm_tc_kernel<<<dim3(GXN / 64, ROWS / 128), 256, GT_SMEM>>>();
    recur_kernel<<<NBLK, 512, RECUR_SMEM>>>();
    head_kernel<<<ROWS / 8, 256>>>(Wfc, bfc, out);
    fin_kernel<<<64, 512>>>(out);
}

// round 11
// speedup vs baseline: 1.7176x; 1.0004x over previous
#include <cuda_runtime.h>
#include <cuda_bf16.h>

typedef unsigned long long ull;

#define Bsz 64
#define Ssz 512
#define Dsz 256
#define Hsz 512
#define ROWS (Bsz * Ssz)   /* 32768 */
#define GXN  (4 * Hsz)     /* 2048  */
#define NBLK 128           /* persistent CTAs (all resident on 148 SMs) */

// ---------------------------------------------------------------------------
// Static device scratch
// ---------------------------------------------------------------------------
__device__ float g_gxq[(size_t)ROWS * GXN];   // [b*512+t][j*4+gate]
__device__ float g_hs[(size_t)ROWS * Hsz];    // [b*512+t][j]
__device__ float g_hbuf[2][Bsz * Hsz];        // double-buffered h
__device__ float g_c[Bsz * Hsz];
__device__ float g_bq[GXN];
// U packed for recurrence: ull pairs (U_g[2p][j], U_g[2p+1][j])
// layout: [jg(64)][p(256)][j8(8)][g(4)]  (ull)
__device__ ull g_Uq[64 * 256 * 8 * 4];
__device__ unsigned g_count;
__device__ unsigned g_gen;
// bf16 split operands for the tensor-core input GEMM
__device__ __nv_bfloat16 g_xhi[(size_t)ROWS * Dsz];
__device__ __nv_bfloat16 g_xlo[(size_t)ROWS * Dsz];
__device__ __nv_bfloat16 g_Wthi[(size_t)GXN * Dsz];   // [n][k] (n = j*4+gate)
__device__ __nv_bfloat16 g_Wtlo[(size_t)GXN * Dsz];

// ---------------------------------------------------------------------------
// f32x2 + sync helpers
// ---------------------------------------------------------------------------
__device__ __forceinline__ ull fma2(ull a, ull b, ull c) {
    ull d; asm("fma.rn.f32x2 %0, %1, %2, %3;" : "=l"(d) : "l"(a), "l"(b), "l"(c)); return d;
}
__device__ __forceinline__ ull pk2(float lo, float hi) {
    ull d; asm("mov.b64 %0, {%1, %2};" : "=l"(d) : "f"(lo), "f"(hi)); return d;
}
__device__ __forceinline__ float2 upk(ull a) {
    float2 r; asm("mov.b64 {%0, %1}, %2;" : "=f"(r.x), "=f"(r.y) : "l"(a)); return r;
}
__device__ __forceinline__ unsigned ld_acq(const unsigned* p) {
    unsigned v; asm volatile("ld.acquire.gpu.b32 %0, [%1];" : "=r"(v) : "l"(p)); return v;
}
__device__ __forceinline__ float sigmoidf_(float x) { return 1.0f / (1.0f + __expf(-x)); }
__device__ __forceinline__ float tanhf_(float x)    { return 1.0f - 2.0f / (__expf(2.0f * x) + 1.0f); }

__device__ __forceinline__ unsigned smem_u32(const void* p) {
    unsigned a;
    asm("{ .reg .u64 t; cvta.to.shared.u64 t, %1; cvt.u32.u64 %0, t; }" : "=r"(a) : "l"(p));
    return a;
}
__device__ __forceinline__ void ldsm4(unsigned& r0, unsigned& r1, unsigned& r2, unsigned& r3,
                                      unsigned addr) {
    asm volatile("ldmatrix.sync.aligned.m8n8.x4.shared.b16 {%0,%1,%2,%3}, [%4];"
                 : "=r"(r0), "=r"(r1), "=r"(r2), "=r"(r3) : "r"(addr));
}
__device__ __forceinline__ void mma_bf16(float& c0, float& c1, float& c2, float& c3,
                                         unsigned a0, unsigned a1, unsigned a2, unsigned a3,
                                         unsigned b0, unsigned b1) {
    asm volatile("mma.sync.aligned.m16n8k16.row.col.f32.bf16.bf16.f32 "
                 "{%0,%1,%2,%3}, {%4,%5,%6,%7}, {%8,%9}, {%0,%1,%2,%3};"
                 : "+f"(c0), "+f"(c1), "+f"(c2), "+f"(c3)
                 : "r"(a0), "r"(a1), "r"(a2), "r"(a3), "r"(b0), "r"(b1));
}

// ---------------------------------------------------------------------------
// Launch 0: split x into bf16 hi/lo
// ---------------------------------------------------------------------------
__global__ void splitx_kernel(const float* __restrict__ x) {
    size_t i = (size_t)blockIdx.x * blockDim.x + threadIdx.x;   // ROWS*Dsz
    float v = x[i];
    __nv_bfloat16 hi = __float2bfloat16(v);
    g_xhi[i] = hi;
    g_xlo[i] = __float2bfloat16(v - __bfloat162float(hi));
}

// ---------------------------------------------------------------------------
// Launch 1: fused prep — packu (blocks 0..2047), packwt+bias (2048..4095),
//           init h0+counters (4096..4223)
// ---------------------------------------------------------------------------
__global__ void prep_kernel(const float* __restrict__ Wf, const float* __restrict__ Wi,
                            const float* __restrict__ Wo, const float* __restrict__ Wc,
                            const float* __restrict__ bf, const float* __restrict__ bi,
                            const float* __restrict__ bo, const float* __restrict__ bc,
                            const float* __restrict__ Uf, const float* __restrict__ Ui,
                            const float* __restrict__ Uo, const float* __restrict__ Uc) {
    const int blk = blockIdx.x;
    const int tid = threadIdx.x;
    if (blk < 2048) {
        // pack U into k-pair ull layout [jg][p][j8][g]
        int idx = blk * 256 + tid;                         // 0..524287
        int p = idx >> 11;
        int rem = idx & 2047;
        int j = rem >> 2;
        int g = rem & 3;
        const float* Ug = (g == 0) ? Uf : (g == 1) ? Ui : (g == 2) ? Uo : Uc;
        float lo = Ug[(size_t)(2 * p) * Hsz + j];
        float hi = Ug[(size_t)(2 * p + 1) * Hsz + j];
        int jg = j >> 3, j8 = j & 7;
        g_Uq[(((size_t)jg * 256 + p) * 8 + j8) * 4 + g] = pk2(lo, hi);
    } else if (blk < 4096) {
        // W transposed bf16 hi/lo: Wt[n][k] = W_{g}[k][j], n = j*4+g; bias at k==0
        int idx = (blk - 2048) * 256 + tid;                // 0..524287
        int n = idx >> 8;                                  // 0..2047
        int k = idx & 255;
        int j = n >> 2, g = n & 3;
        const float* Wg = (g == 0) ? Wf : (g == 1) ? Wi : (g == 2) ? Wo : Wc;
        float v = Wg[(size_t)k * Hsz + j];
        __nv_bfloat16 hi = __float2bfloat16(v);
        g_Wthi[(size_t)n * Dsz + k] = hi;
        g_Wtlo[(size_t)n * Dsz + k] = __float2bfloat16(v - __bfloat162float(hi));
        if (k == 0) {
            const float* bg = (g == 0) ? bf : (g == 1) ? bi : (g == 2) ? bo : bc;
            g_bq[n] = bg[j];
        }
    } else {
        // init h0 + barrier counters
        int i = (blk - 4096) * 256 + tid;                  // 0..32767
        g_hbuf[0][i] = 0.0f;
        if (i == 0) { g_count = 0u; g_gen = 0u; }
    }
}

// ---------------------------------------------------------------------------
// Launch 2: mma.sync bf16 split-precision input GEMM (unchanged from R10)
// ---------------------------------------------------------------------------
#define SB_ST   264
#define SA_ST   40
#define SB_HI   0
#define SB_LO   (64 * SB_ST * 2)
#define SA_HI   (2 * 64 * SB_ST * 2)
#define SA_LO   (SA_HI + 128 * SA_ST * 2)
#define GT_SMEM (SA_LO + 128 * SA_ST * 2)     /* 88064 */

__global__ void __launch_bounds__(256, 2)
gemm_tc_kernel() {
    extern __shared__ char smem[];
    const unsigned sbase = smem_u32(smem);

    const int tid  = threadIdx.x;
    const int lane = tid & 31;
    const int wid  = tid >> 5;
    const int wm   = wid & 3;
    const int wn   = wid >> 2;
    const int m0w  = wm * 32;
    const int n0w  = wn * 32;
    const int n0   = blockIdx.x * 64;
    const int r0   = blockIdx.y * 128;

    #pragma unroll
    for (int r = 0; r < 8; r++) {
        int v = r * 256 + tid;
        int row = v >> 5, cu = v & 31;
        size_t src = (size_t)(n0 + row) * Dsz + cu * 8;
        *(uint4*)(smem + SB_HI + (row * SB_ST + cu * 8) * 2) = *(const uint4*)&g_Wthi[src];
        *(uint4*)(smem + SB_LO + (row * SB_ST + cu * 8) * 2) = *(const uint4*)&g_Wtlo[src];
    }

    float c[2][4][4];
    #pragma unroll
    for (int mi = 0; mi < 2; mi++)
        #pragma unroll
        for (int ni = 0; ni < 4; ni++)
            #pragma unroll
            for (int e = 0; e < 4; e++) c[mi][ni][e] = 0.0f;

    const int aRow  = lane & 15;
    const int aKoff = (lane >> 4) * 8;
    const int bSel  = lane >> 3;
    const int bRow  = (bSel >> 1) * 8 + (lane & 7);
    const int bKoff = (bSel & 1) * 8;

    for (int kc = 0; kc < 8; kc++) {
        __syncthreads();
        #pragma unroll
        for (int r = 0; r < 2; r++) {
            int v = r * 256 + tid;
            int row = v >> 2, cu = v & 3;
            size_t src = (size_t)(r0 + row) * Dsz + kc * 32 + cu * 8;
            *(uint4*)(smem + SA_HI + (row * SA_ST + cu * 8) * 2) = *(const uint4*)&g_xhi[src];
            *(uint4*)(smem + SA_LO + (row * SA_ST + cu * 8) * 2) = *(const uint4*)&g_xlo[src];
        }
        __syncthreads();

        #pragma unroll
        for (int ks = 0; ks < 2; ks++) {
            const int kchunk = ks * 16;
            const int kglob  = kc * 32 + kchunk;

            unsigned ah[2][4], al[2][4];
            #pragma unroll
            for (int mi = 0; mi < 2; mi++) {
                unsigned off = (unsigned)((m0w + mi * 16 + aRow) * SA_ST + kchunk + aKoff) * 2;
                ldsm4(ah[mi][0], ah[mi][1], ah[mi][2], ah[mi][3], sbase + SA_HI + off);
                ldsm4(al[mi][0], al[mi][1], al[mi][2], al[mi][3], sbase + SA_LO + off);
            }
            unsigned bh[4][2], bl[4][2];
            #pragma unroll
            for (int half = 0; half < 2; half++) {
                unsigned off = (unsigned)((n0w + half * 16 + bRow) * SB_ST + kglob + bKoff) * 2;
                ldsm4(bh[half * 2][0], bh[half * 2][1], bh[half * 2 + 1][0], bh[half * 2 + 1][1],
                      sbase + SB_HI + off);
                ldsm4(bl[half * 2][0], bl[half * 2][1], bl[half * 2 + 1][0], bl[half * 2 + 1][1],
                      sbase + SB_LO + off);
            }

            #pragma unroll
            for (int mi = 0; mi < 2; mi++)
                #pragma unroll
                for (int ni = 0; ni < 4; ni++) {
                    float* cc = c[mi][ni];
                    mma_bf16(cc[0], cc[1], cc[2], cc[3],
                             ah[mi][0], ah[mi][1], ah[mi][2], ah[mi][3],
                             bh[ni][0], bh[ni][1]);
                    mma_bf16(cc[0], cc[1], cc[2], cc[3],
                             ah[mi][0], ah[mi][1], ah[mi][2], ah[mi][3],
                             bl[ni][0], bl[ni][1]);
                    mma_bf16(cc[0], cc[1], cc[2], cc[3],
                             al[mi][0], al[mi][1], al[mi][2], al[mi][3],
                             bh[ni][0], bh[ni][1]);
                }
        }
    }

    const int crow = lane >> 2;
    const int ccol = (lane & 3) * 2;
    #pragma unroll
    for (int mi = 0; mi < 2; mi++) {
        #pragma unroll
        for (int ni = 0; ni < 4; ni++) {
            int col = n0 + n0w + ni * 8 + ccol;
            float2 bb = *(const float2*)&g_bq[col];
            int m1 = r0 + m0w + mi * 16 + crow;
            float2 o0; o0.x = c[mi][ni][0] + bb.x; o0.y = c[mi][ni][1] + bb.y;
            float2 o1; o1.x = c[mi][ni][2] + bb.x; o1.y = c[mi][ni][3] + bb.y;
            *(float2*)&g_gxq[(size_t)m1 * GXN + col] = o0;
            *(float2*)&g_gxq[(size_t)(m1 + 8) * GXN + col] = o1;
        }
    }
}

// ---------------------------------------------------------------------------
// Launch 3 (PROFILED): persistent LSTM recurrence — byte-identical to best
// ---------------------------------------------------------------------------
#define SU_BYTES  (256 * 8 * 48)                 /* 98304 */
#define SH_OFF    SU_BYTES
#define SH_STRIDE 516
#define SH_BYTES  (32 * SH_STRIDE * 4)           /* 66048 */
#define SRED_OFF  (SH_OFF + SH_BYTES)            /* 164352 */
#define SRED_BYTES (3 * 256 * 16)                /* 12288 */
#define RECUR_SMEM (SRED_OFF + SRED_BYTES)       /* 176640 */

__global__ void __launch_bounds__(512, 1)
recur_kernel() {
    extern __shared__ char smem[];
    char*  sU   = smem;
    float* sH   = (float*)(smem + SH_OFF);
    float4* sRed = (float4*)(smem + SRED_OFF);

    const int tid = threadIdx.x;
    const int j8  = tid & 7;
    const int bp  = (tid >> 3) & 15;
    const int ks  = tid >> 7;
    const int jg  = blockIdx.x >> 1;
    const int bg  = blockIdx.x & 1;
    const int j   = jg * 8 + j8;
    const int b0g = bg * 32 + bp;
    const int b1g = b0g + 16;

    {
        const ull* uq = &g_Uq[(size_t)jg * 8192];
        for (int r = 0; r < 16; r++) {
            int v = r * 512 + tid;
            int p = v >> 5, jj = (v >> 2) & 7, g = v & 3;
            *(ull*)(sU + p * 384 + jj * 48 + g * 8) = uq[v];
        }
    }

    const char* uBase = sU + j8 * 48 + ks * 64 * 384;
    float c0 = 0.0f, c1 = 0.0f;

    for (int t = 0; t < Ssz; t++) {
        const float* hp = g_hbuf[t & 1];

        float4 gx0, gx1;
        if (ks == 0) {
            gx0 = *(const float4*)&g_gxq[(size_t)(b0g * Ssz + t) * GXN + j * 4];
            gx1 = *(const float4*)&g_gxq[(size_t)(b1g * Ssz + t) * GXN + j * 4];
        }

        #pragma unroll
        for (int r = 0; r < 8; r++) {
            int v = r * 512 + tid;
            int row = v >> 7, c4 = v & 127;
            float4 f = __ldcg((const float4*)&hp[(bg * 32 + row) * Hsz + c4 * 4]);
            *(float4*)&sH[row * SH_STRIDE + c4 * 4] = f;
        }
        __syncthreads();

        ull aF0 = 0, aI0 = 0, aO0 = 0, aC0 = 0;
        ull aF1 = 0, aI1 = 0, aO1 = 0, aC1 = 0;
        {
            const ulonglong2* hA = (const ulonglong2*)&sH[bp * SH_STRIDE + ks * 128];
            const ulonglong2* hB = (const ulonglong2*)&sH[(bp + 16) * SH_STRIDE + ks * 128];
            const char* up = uBase;
            #pragma unroll 8
            for (int i = 0; i < 32; i++) {
                ulonglong2 ufi0 = *(const ulonglong2*)(up);
                ulonglong2 uoc0 = *(const ulonglong2*)(up + 16);
                ulonglong2 ufi1 = *(const ulonglong2*)(up + 384);
                ulonglong2 uoc1 = *(const ulonglong2*)(up + 400);
                ulonglong2 ha = hA[i];
                ulonglong2 hb = hB[i];
                aF0 = fma2(ufi0.x, ha.x, aF0);  aI0 = fma2(ufi0.y, ha.x, aI0);
                aO0 = fma2(uoc0.x, ha.x, aO0);  aC0 = fma2(uoc0.y, ha.x, aC0);
                aF1 = fma2(ufi0.x, hb.x, aF1);  aI1 = fma2(ufi0.y, hb.x, aI1);
                aO1 = fma2(uoc0.x, hb.x, aO1);  aC1 = fma2(uoc0.y, hb.x, aC1);
                aF0 = fma2(ufi1.x, ha.y, aF0);  aI0 = fma2(ufi1.y, ha.y, aI0);
                aO0 = fma2(uoc1.x, ha.y, aO0);  aC0 = fma2(uoc1.y, ha.y, aC0);
                aF1 = fma2(ufi1.x, hb.y, aF1);  aI1 = fma2(ufi1.y, hb.y, aI1);
                aO1 = fma2(uoc1.x, hb.y, aO1);  aC1 = fma2(uoc1.y, hb.y, aC1);
                up += 768;
            }
        }

        float2 t2;
        float4 p0, p1;
        t2 = upk(aF0); p0.x = t2.x + t2.y;   t2 = upk(aI0); p0.y = t2.x + t2.y;
        t2 = upk(aO0); p0.z = t2.x + t2.y;   t2 = upk(aC0); p0.w = t2.x + t2.y;
        t2 = upk(aF1); p1.x = t2.x + t2.y;   t2 = upk(aI1); p1.y = t2.x + t2.y;
        t2 = upk(aO1); p1.z = t2.x + t2.y;   t2 = upk(aC1); p1.w = t2.x + t2.y;

        int cell0 = bp * 8 + j8;
        if (ks != 0) {
            sRed[(ks - 1) * 256 + cell0]       = p0;
            sRed[(ks - 1) * 256 + cell0 + 128] = p1;
        }
        __syncthreads();

        if (ks == 0) {
            float4 q0 = sRed[cell0],        q1 = sRed[256 + cell0],        q2 = sRed[512 + cell0];
            float4 r0_ = sRed[cell0 + 128], r1_ = sRed[256 + cell0 + 128], r2_ = sRed[512 + cell0 + 128];
            float pf0 = gx0.x + p0.x + q0.x + q1.x + q2.x;
            float pi0 = gx0.y + p0.y + q0.y + q1.y + q2.y;
            float po0 = gx0.z + p0.z + q0.z + q1.z + q2.z;
            float pc0 = gx0.w + p0.w + q0.w + q1.w + q2.w;
            float pf1 = gx1.x + p1.x + r0_.x + r1_.x + r2_.x;
            float pi1 = gx1.y + p1.y + r0_.y + r1_.y + r2_.y;
            float po1 = gx1.z + p1.z + r0_.z + r1_.z + r2_.z;
            float pc1 = gx1.w + p1.w + r0_.w + r1_.w + r2_.w;

            c0 = sigmoidf_(pf0) * c0 + sigmoidf_(pi0) * tanhf_(pc0);
            float h0 = sigmoidf_(po0) * tanhf_(c0);
            c1 = sigmoidf_(pf1) * c1 + sigmoidf_(pi1) * tanhf_(pc1);
            float h1 = sigmoidf_(po1) * tanhf_(c1);

            float* hn = g_hbuf[(t + 1) & 1];
            hn[b0g * Hsz + j] = h0;
            hn[b1g * Hsz + j] = h1;
            g_hs[(size_t)(b0g * Ssz + t) * Hsz + j] = h0;
            g_hs[(size_t)(b1g * Ssz + t) * Hsz + j] = h1;
        }

        __threadfence();
        __syncthreads();
        if (tid == 0) {
            unsigned target = (unsigned)NBLK * (unsigned)(t + 1);
            unsigned prev = atomicAdd(&g_count, 1u);
            if (prev + 1u == target) {
                atomicExch(&g_gen, (unsigned)(t + 1));
            } else {
                long long spins = 0;
                while (ld_acq(&g_gen) < (unsigned)(t + 1)) {
                    __nanosleep(64);
                    if (++spins > 100000000LL) break;
                }
            }
        }
        __syncthreads();
    }

    if (ks == 0) {
        g_c[b0g * Hsz + j] = c0;
        g_c[b1g * Hsz + j] = c1;
    }
}

// ---------------------------------------------------------------------------
// Launch 4: fused output head + final-state copy
//   blocks [0,4096): head (8 warps per block, 1 warp per (b,t) row)
//   blocks [4096,4160): fin copy
// ---------------------------------------------------------------------------
__global__ void headfin_kernel(const float* __restrict__ Wfc, const float* __restrict__ bfc,
                               float* __restrict__ out) {
    const int blk = blockIdx.x;
    if (blk < 4096) {
        int warp = blk * 8 + ((int)threadIdx.x >> 5);
        int lane = threadIdx.x & 31;
        const float* hrow = &g_hs[(size_t)warp * Hsz];
        float acc = 0.0f;
        #pragma unroll
        for (int q = 0; q < 4; q++) {
            float4 h = *(const float4*)&hrow[q * 128 + lane * 4];
            float4 w = *(const float4*)&Wfc[q * 128 + lane * 4];
            acc += h.x * w.x + h.y * w.y + h.z * w.z + h.w * w.w;
        }
        #pragma unroll
        for (int s = 16; s > 0; s >>= 1) acc += __shfl_xor_sync(0xFFFFFFFFu, acc, s);
        if (lane == 0) out[warp] = acc + bfc[0];
    } else {
        int i = (blk - 4096) * 256 + threadIdx.x;   // 0..16383 * 2
        // cover 32768 elems with 64 blocks x 256 thr x 2
        #pragma unroll
        for (int r = 0; r < 2; r++) {
            int v = i * 2 + r;
            out[32768 + v] = g_hbuf[0][v];
            out[65536 + v] = g_c[v];
        }
    }
}

// ---------------------------------------------------------------------------
extern "C" void kernel_launch(void* const* d_in, const int* in_sizes, int n_in,
                              void* d_out, int out_size) {
    const float* x   = (const float*)d_in[0];
    const float* Wf  = (const float*)d_in[1];
    const float* Wi  = (const float*)d_in[2];
    const float* Wo  = (const float*)d_in[3];
    const float* Wc  = (const float*)d_in[4];
    const float* bf  = (const float*)d_in[5];
    const float* bi  = (const float*)d_in[6];
    const float* bo  = (const float*)d_in[7];
    const float* bc  = (const float*)d_in[8];
    const float* Uf  = (const float*)d_in[9];
    const float* Ui  = (const float*)d_in[10];
    const float* Uo  = (const float*)d_in[11];
    const float* Uc  = (const float*)d_in[12];
    const float* Wfc = (const float*)d_in[13];
    const float* bfc = (const float*)d_in[14];
    float* out = (float*)d_out;

    cudaFuncSetAttribute(recur_kernel, cudaFuncAttributeMaxDynamicSharedMemorySize, RECUR_SMEM);
    cudaFuncSetAttribute(gemm_tc_kernel, cudaFuncAttributeMaxDynamicSharedMemorySize, GT_SMEM);

    splitx_kernel<<<ROWS * Dsz / 256, 256>>>(x);                       // launch 0
    prep_kernel<<<4224, 256>>>(Wf, Wi, Wo, Wc, bf, bi, bo, bc,
                               Uf, Ui, Uo, Uc);                        // launch 1
    gemm_tc_kernel<<<dim3(GXN / 64, ROWS / 128), 256, GT_SMEM>>>();    // launch 2
    recur_kernel<<<NBLK, 512, RECUR_SMEM>>>();                         // launch 3 (profiled)
    headfin_kernel<<<4096 + 64, 256>>>(Wfc, bfc, out);                 // launch 4
}

// round 12
// speedup vs baseline: 1.9123x; 1.1134x over previous
#include <cuda_runtime.h>
#include <cuda_bf16.h>

typedef unsigned long long ull;

#define Bsz 64
#define Ssz 512
#define Dsz 256
#define Hsz 512
#define ROWS (Bsz * Ssz)   /* 32768 */
#define GXN  (4 * Hsz)     /* 2048  */
#define NBLK 128           /* persistent CTAs (all resident on 148 SMs) */

// ---------------------------------------------------------------------------
// Static device scratch
// ---------------------------------------------------------------------------
__device__ float g_gxq[(size_t)ROWS * GXN];   // [b*512+t][j*4+gate]
__device__ float g_hs[(size_t)ROWS * Hsz];    // [b*512+t][j]
__device__ float g_hbuf[2][Bsz * Hsz];        // double-buffered h
__device__ float g_c[Bsz * Hsz];
__device__ float g_bq[GXN];
// U packed for recurrence: ull pairs (U_g[2p][j], U_g[2p+1][j])
// layout: [jg(64)][p(256)][j8(8)][g(4)]  (ull)
__device__ ull g_Uq[64 * 256 * 8 * 4];
__device__ unsigned g_count;
__device__ unsigned g_gen;
// bf16 split operands for the tensor-core input GEMM
__device__ __nv_bfloat16 g_xhi[(size_t)ROWS * Dsz];
__device__ __nv_bfloat16 g_xlo[(size_t)ROWS * Dsz];
__device__ __nv_bfloat16 g_Wthi[(size_t)GXN * Dsz];   // [n][k] (n = j*4+gate)
__device__ __nv_bfloat16 g_Wtlo[(size_t)GXN * Dsz];

// ---------------------------------------------------------------------------
// f32x2 + sync helpers
// ---------------------------------------------------------------------------
__device__ __forceinline__ ull fma2(ull a, ull b, ull c) {
    ull d; asm("fma.rn.f32x2 %0, %1, %2, %3;" : "=l"(d) : "l"(a), "l"(b), "l"(c)); return d;
}
__device__ __forceinline__ ull pk2(float lo, float hi) {
    ull d; asm("mov.b64 %0, {%1, %2};" : "=l"(d) : "f"(lo), "f"(hi)); return d;
}
__device__ __forceinline__ float2 upk(ull a) {
    float2 r; asm("mov.b64 {%0, %1}, %2;" : "=f"(r.x), "=f"(r.y) : "l"(a)); return r;
}
__device__ __forceinline__ unsigned ld_acq(const unsigned* p) {
    unsigned v; asm volatile("ld.acquire.gpu.b32 %0, [%1];" : "=r"(v) : "l"(p)); return v;
}
__device__ __forceinline__ float sigmoidf_(float x) { return 1.0f / (1.0f + __expf(-x)); }
__device__ __forceinline__ float tanhf_(float x)    { return 1.0f - 2.0f / (__expf(2.0f * x) + 1.0f); }

__device__ __forceinline__ unsigned smem_u32(const void* p) {
    unsigned a;
    asm("{ .reg .u64 t; cvta.to.shared.u64 t, %1; cvt.u32.u64 %0, t; }" : "=r"(a) : "l"(p));
    return a;
}
__device__ __forceinline__ void ldsm4(unsigned& r0, unsigned& r1, unsigned& r2, unsigned& r3,
                                      unsigned addr) {
    asm volatile("ldmatrix.sync.aligned.m8n8.x4.shared.b16 {%0,%1,%2,%3}, [%4];"
                 : "=r"(r0), "=r"(r1), "=r"(r2), "=r"(r3) : "r"(addr));
}
__device__ __forceinline__ void mma_bf16(float& c0, float& c1, float& c2, float& c3,
                                         unsigned a0, unsigned a1, unsigned a2, unsigned a3,
                                         unsigned b0, unsigned b1) {
    asm volatile("mma.sync.aligned.m16n8k16.row.col.f32.bf16.bf16.f32 "
                 "{%0,%1,%2,%3}, {%4,%5,%6,%7}, {%8,%9}, {%0,%1,%2,%3};"
                 : "+f"(c0), "+f"(c1), "+f"(c2), "+f"(c3)
                 : "r"(a0), "r"(a1), "r"(a2), "r"(a3), "r"(b0), "r"(b1));
}

// ---------------------------------------------------------------------------
// Launch 0: split x into bf16 hi/lo
// ---------------------------------------------------------------------------
__global__ void splitx_kernel(const float* __restrict__ x) {
    size_t i = (size_t)blockIdx.x * blockDim.x + threadIdx.x;   // ROWS*Dsz
    float v = x[i];
    __nv_bfloat16 hi = __float2bfloat16(v);
    g_xhi[i] = hi;
    g_xlo[i] = __float2bfloat16(v - __bfloat162float(hi));
}

// ---------------------------------------------------------------------------
// Launch 1: fused prep — packu (blocks 0..2047), packwt+bias (2048..4095),
//           init h0+counters (4096..4223)
// ---------------------------------------------------------------------------
__global__ void prep_kernel(const float* __restrict__ Wf, const float* __restrict__ Wi,
                            const float* __restrict__ Wo, const float* __restrict__ Wc,
                            const float* __restrict__ bf, const float* __restrict__ bi,
                            const float* __restrict__ bo, const float* __restrict__ bc,
                            const float* __restrict__ Uf, const float* __restrict__ Ui,
                            const float* __restrict__ Uo, const float* __restrict__ Uc) {
    const int blk = blockIdx.x;
    const int tid = threadIdx.x;
    if (blk < 2048) {
        int idx = blk * 256 + tid;                         // 0..524287
        int p = idx >> 11;
        int rem = idx & 2047;
        int j = rem >> 2;
        int g = rem & 3;
        const float* Ug = (g == 0) ? Uf : (g == 1) ? Ui : (g == 2) ? Uo : Uc;
        float lo = Ug[(size_t)(2 * p) * Hsz + j];
        float hi = Ug[(size_t)(2 * p + 1) * Hsz + j];
        int jg = j >> 3, j8 = j & 7;
        g_Uq[(((size_t)jg * 256 + p) * 8 + j8) * 4 + g] = pk2(lo, hi);
    } else if (blk < 4096) {
        int idx = (blk - 2048) * 256 + tid;                // 0..524287
        int n = idx >> 8;                                  // 0..2047
        int k = idx & 255;
        int j = n >> 2, g = n & 3;
        const float* Wg = (g == 0) ? Wf : (g == 1) ? Wi : (g == 2) ? Wo : Wc;
        float v = Wg[(size_t)k * Hsz + j];
        __nv_bfloat16 hi = __float2bfloat16(v);
        g_Wthi[(size_t)n * Dsz + k] = hi;
        g_Wtlo[(size_t)n * Dsz + k] = __float2bfloat16(v - __bfloat162float(hi));
        if (k == 0) {
            const float* bg = (g == 0) ? bf : (g == 1) ? bi : (g == 2) ? bo : bc;
            g_bq[n] = bg[j];
        }
    } else {
        int i = (blk - 4096) * 256 + tid;                  // 0..32767
        g_hbuf[0][i] = 0.0f;
        if (i == 0) { g_count = 0u; g_gen = 0u; }
    }
}

// ---------------------------------------------------------------------------
// Launch 2: mma.sync bf16 split-precision input GEMM (unchanged, measured good)
// ---------------------------------------------------------------------------
#define SB_ST   264
#define SA_ST   40
#define SB_HI   0
#define SB_LO   (64 * SB_ST * 2)
#define SA_HI   (2 * 64 * SB_ST * 2)
#define SA_LO   (SA_HI + 128 * SA_ST * 2)
#define GT_SMEM (SA_LO + 128 * SA_ST * 2)     /* 88064 */

__global__ void __launch_bounds__(256, 2)
gemm_tc_kernel() {
    extern __shared__ char smem[];
    const unsigned sbase = smem_u32(smem);

    const int tid  = threadIdx.x;
    const int lane = tid & 31;
    const int wid  = tid >> 5;
    const int wm   = wid & 3;
    const int wn   = wid >> 2;
    const int m0w  = wm * 32;
    const int n0w  = wn * 32;
    const int n0   = blockIdx.x * 64;
    const int r0   = blockIdx.y * 128;

    #pragma unroll
    for (int r = 0; r < 8; r++) {
        int v = r * 256 + tid;
        int row = v >> 5, cu = v & 31;
        size_t src = (size_t)(n0 + row) * Dsz + cu * 8;
        *(uint4*)(smem + SB_HI + (row * SB_ST + cu * 8) * 2) = *(const uint4*)&g_Wthi[src];
        *(uint4*)(smem + SB_LO + (row * SB_ST + cu * 8) * 2) = *(const uint4*)&g_Wtlo[src];
    }

    float c[2][4][4];
    #pragma unroll
    for (int mi = 0; mi < 2; mi++)
        #pragma unroll
        for (int ni = 0; ni < 4; ni++)
            #pragma unroll
            for (int e = 0; e < 4; e++) c[mi][ni][e] = 0.0f;

    const int aRow  = lane & 15;
    const int aKoff = (lane >> 4) * 8;
    const int bSel  = lane >> 3;
    const int bRow  = (bSel >> 1) * 8 + (lane & 7);
    const int bKoff = (bSel & 1) * 8;

    for (int kc = 0; kc < 8; kc++) {
        __syncthreads();
        #pragma unroll
        for (int r = 0; r < 2; r++) {
            int v = r * 256 + tid;
            int row = v >> 2, cu = v & 3;
            size_t src = (size_t)(r0 + row) * Dsz + kc * 32 + cu * 8;
            *(uint4*)(smem + SA_HI + (row * SA_ST + cu * 8) * 2) = *(const uint4*)&g_xhi[src];
            *(uint4*)(smem + SA_LO + (row * SA_ST + cu * 8) * 2) = *(const uint4*)&g_xlo[src];
        }
        __syncthreads();

        #pragma unroll
        for (int ks = 0; ks < 2; ks++) {
            const int kchunk = ks * 16;
            const int kglob  = kc * 32 + kchunk;

            unsigned ah[2][4], al[2][4];
            #pragma unroll
            for (int mi = 0; mi < 2; mi++) {
                unsigned off = (unsigned)((m0w + mi * 16 + aRow) * SA_ST + kchunk + aKoff) * 2;
                ldsm4(ah[mi][0], ah[mi][1], ah[mi][2], ah[mi][3], sbase + SA_HI + off);
                ldsm4(al[mi][0], al[mi][1], al[mi][2], al[mi][3], sbase + SA_LO + off);
            }
            unsigned bh[4][2], bl[4][2];
            #pragma unroll
            for (int half = 0; half < 2; half++) {
                unsigned off = (unsigned)((n0w + half * 16 + bRow) * SB_ST + kglob + bKoff) * 2;
                ldsm4(bh[half * 2][0], bh[half * 2][1], bh[half * 2 + 1][0], bh[half * 2 + 1][1],
                      sbase + SB_HI + off);
                ldsm4(bl[half * 2][0], bl[half * 2][1], bl[half * 2 + 1][0], bl[half * 2 + 1][1],
                      sbase + SB_LO + off);
            }

            #pragma unroll
            for (int mi = 0; mi < 2; mi++)
                #pragma unroll
                for (int ni = 0; ni < 4; ni++) {
                    float* cc = c[mi][ni];
                    mma_bf16(cc[0], cc[1], cc[2], cc[3],
                             ah[mi][0], ah[mi][1], ah[mi][2], ah[mi][3],
                             bh[ni][0], bh[ni][1]);
                    mma_bf16(cc[0], cc[1], cc[2], cc[3],
                             ah[mi][0], ah[mi][1], ah[mi][2], ah[mi][3],
                             bl[ni][0], bl[ni][1]);
                    mma_bf16(cc[0], cc[1], cc[2], cc[3],
                             al[mi][0], al[mi][1], al[mi][2], al[mi][3],
                             bh[ni][0], bh[ni][1]);
                }
        }
    }

    const int crow = lane >> 2;
    const int ccol = (lane & 3) * 2;
    #pragma unroll
    for (int mi = 0; mi < 2; mi++) {
        #pragma unroll
        for (int ni = 0; ni < 4; ni++) {
            int col = n0 + n0w + ni * 8 + ccol;
            float2 bb = *(const float2*)&g_bq[col];
            int m1 = r0 + m0w + mi * 16 + crow;
            float2 o0; o0.x = c[mi][ni][0] + bb.x; o0.y = c[mi][ni][1] + bb.y;
            float2 o1; o1.x = c[mi][ni][2] + bb.x; o1.y = c[mi][ni][3] + bb.y;
            *(float2*)&g_gxq[(size_t)m1 * GXN + col] = o0;
            *(float2*)&g_gxq[(size_t)(m1 + 8) * GXN + col] = o1;
        }
    }
}

// ---------------------------------------------------------------------------
// Launch 3 (PROFILED): persistent LSTM recurrence — 4-cell b-tiling, 8-way k
//   thread: j8 = tid&7, bp = (tid>>3)&7, ks = tid>>6 (8-way, k=64 each)
//   cells: b = bg*32 + bp + {0,8,16,24}, column j. Every U load feeds 4 cells:
//   per 4-k iter: 4 U LDS.128 + 4 h LDS.128 -> 32 fma2 (was 6 LDS -> 16 fma2).
// ---------------------------------------------------------------------------
#define SU_BYTES  (256 * 8 * 48)                 /* 98304 */
#define SH_OFF    SU_BYTES
#define SH_STRIDE 516
#define SH_BYTES  (32 * SH_STRIDE * 4)           /* 66048 */
#define SRED_OFF  (SH_OFF + SH_BYTES)            /* 164352 */
#define SRED_BYTES (7 * 256 * 16)                /* 28672 */
#define RECUR_SMEM (SRED_OFF + SRED_BYTES)       /* 193024 */

__global__ void __launch_bounds__(512, 1)
recur_kernel() {
    extern __shared__ char smem[];
    char*  sU   = smem;
    float* sH   = (float*)(smem + SH_OFF);
    float4* sRed = (float4*)(smem + SRED_OFF);

    const int tid = threadIdx.x;
    const int j8  = tid & 7;
    const int bp  = (tid >> 3) & 7;      // 0..7
    const int ks  = tid >> 6;            // 0..7 (k-slice of 64)
    const int jg  = blockIdx.x >> 1;
    const int bg  = blockIdx.x & 1;
    const int j   = jg * 8 + j8;

    // ---- load U slice into bank-perfect padded SMEM (once) ----
    {
        const ull* uq = &g_Uq[(size_t)jg * 8192];
        for (int r = 0; r < 16; r++) {
            int v = r * 512 + tid;               // 0..8191 ull
            int p = v >> 5, jj = (v >> 2) & 7, g = v & 3;
            *(ull*)(sU + p * 384 + jj * 48 + g * 8) = uq[v];
        }
    }

    const char* uBase = sU + j8 * 48 + ks * 32 * 384;   // 32 p per ks slice
    float cst[4] = {0.0f, 0.0f, 0.0f, 0.0f};

    for (int t = 0; t < Ssz; t++) {
        const float* hp = g_hbuf[t & 1];

        // gx prefetch for epilogue (ks==0 threads = tid<64)
        float4 gx[4];
        if (ks == 0) {
            #pragma unroll
            for (int c = 0; c < 4; c++)
                gx[c] = *(const float4*)
                    &g_gxq[(size_t)((bg * 32 + bp + c * 8) * Ssz + t) * GXN + j * 4];
        }

        // ---- stage h into SMEM (32 rows x 512, pad 516), L2-coherent ----
        #pragma unroll 4
        for (int r = 0; r < 8; r++) {
            int v = r * 512 + tid;               // float4 index 0..4095
            int row = v >> 7, c4 = v & 127;
            float4 f = __ldcg((const float4*)&hp[(bg * 32 + row) * Hsz + c4 * 4]);
            *(float4*)&sH[row * SH_STRIDE + c4 * 4] = f;
        }
        __syncthreads();

        // ---- main compute: 4 cells, 64-k window, pair-over-k FFMA2 ----
        ull aF[4], aI[4], aO[4], aC[4];
        #pragma unroll
        for (int c = 0; c < 4; c++) { aF[c] = 0; aI[c] = 0; aO[c] = 0; aC[c] = 0; }
        {
            const ulonglong2* hr0 = (const ulonglong2*)&sH[(bp     ) * SH_STRIDE + ks * 64];
            const ulonglong2* hr1 = (const ulonglong2*)&sH[(bp +  8) * SH_STRIDE + ks * 64];
            const ulonglong2* hr2 = (const ulonglong2*)&sH[(bp + 16) * SH_STRIDE + ks * 64];
            const ulonglong2* hr3 = (const ulonglong2*)&sH[(bp + 24) * SH_STRIDE + ks * 64];
            const char* up = uBase;
            #pragma unroll 4
            for (int i = 0; i < 16; i++) {       // 4 k per iter (2 k-pairs)
                ulonglong2 ufi0 = *(const ulonglong2*)(up);
                ulonglong2 uoc0 = *(const ulonglong2*)(up + 16);
                ulonglong2 ufi1 = *(const ulonglong2*)(up + 384);
                ulonglong2 uoc1 = *(const ulonglong2*)(up + 400);
                ulonglong2 h0 = hr0[i];
                ulonglong2 h1 = hr1[i];
                ulonglong2 h2 = hr2[i];
                ulonglong2 h3 = hr3[i];
                aF[0] = fma2(ufi0.x, h0.x, aF[0]);  aI[0] = fma2(ufi0.y, h0.x, aI[0]);
                aO[0] = fma2(uoc0.x, h0.x, aO[0]);  aC[0] = fma2(uoc0.y, h0.x, aC[0]);
                aF[0] = fma2(ufi1.x, h0.y, aF[0]);  aI[0] = fma2(ufi1.y, h0.y, aI[0]);
                aO[0] = fma2(uoc1.x, h0.y, aO[0]);  aC[0] = fma2(uoc1.y, h0.y, aC[0]);
                aF[1] = fma2(ufi0.x, h1.x, aF[1]);  aI[1] = fma2(ufi0.y, h1.x, aI[1]);
                aO[1] = fma2(uoc0.x, h1.x, aO[1]);  aC[1] = fma2(uoc0.y, h1.x, aC[1]);
                aF[1] = fma2(ufi1.x, h1.y, aF[1]);  aI[1] = fma2(ufi1.y, h1.y, aI[1]);
                aO[1] = fma2(uoc1.x, h1.y, aO[1]);  aC[1] = fma2(uoc1.y, h1.y, aC[1]);
                aF[2] = fma2(ufi0.x, h2.x, aF[2]);  aI[2] = fma2(ufi0.y, h2.x, aI[2]);
                aO[2] = fma2(uoc0.x, h2.x, aO[2]);  aC[2] = fma2(uoc0.y, h2.x, aC[2]);
                aF[2] = fma2(ufi1.x, h2.y, aF[2]);  aI[2] = fma2(ufi1.y, h2.y, aI[2]);
                aO[2] = fma2(uoc1.x, h2.y, aO[2]);  aC[2] = fma2(uoc1.y, h2.y, aC[2]);
                aF[3] = fma2(ufi0.x, h3.x, aF[3]);  aI[3] = fma2(ufi0.y, h3.x, aI[3]);
                aO[3] = fma2(uoc0.x, h3.x, aO[3]);  aC[3] = fma2(uoc0.y, h3.x, aC[3]);
                aF[3] = fma2(ufi1.x, h3.y, aF[3]);  aI[3] = fma2(ufi1.y, h3.y, aI[3]);
                aO[3] = fma2(uoc1.x, h3.y, aO[3]);  aC[3] = fma2(uoc1.y, h3.y, aC[3]);
                up += 768;
            }
        }

        // fold f32x2 lanes -> per-cell partial float4
        float4 part[4];
        #pragma unroll
        for (int c = 0; c < 4; c++) {
            float2 t2;
            t2 = upk(aF[c]); part[c].x = t2.x + t2.y;
            t2 = upk(aI[c]); part[c].y = t2.x + t2.y;
            t2 = upk(aO[c]); part[c].z = t2.x + t2.y;
            t2 = upk(aC[c]); part[c].w = t2.x + t2.y;
        }

        const int cell = bp * 8 + j8;            // 0..63 ; full id = cell + c*64
        if (ks != 0) {
            #pragma unroll
            for (int c = 0; c < 4; c++)
                sRed[(ks - 1) * 256 + cell + c * 64] = part[c];
        }
        __syncthreads();

        // ---- epilogue: ks==0 threads (64) reduce 8 slices, gates, write h ----
        if (ks == 0) {
            #pragma unroll
            for (int c = 0; c < 4; c++) {
                float4 acc = part[c];
                #pragma unroll
                for (int s = 0; s < 7; s++) {
                    float4 q = sRed[s * 256 + cell + c * 64];
                    acc.x += q.x; acc.y += q.y; acc.z += q.z; acc.w += q.w;
                }
                float pf = gx[c].x + acc.x;
                float pi = gx[c].y + acc.y;
                float po = gx[c].z + acc.z;
                float pc = gx[c].w + acc.w;

                cst[c] = sigmoidf_(pf) * cst[c] + sigmoidf_(pi) * tanhf_(pc);
                float hn = sigmoidf_(po) * tanhf_(cst[c]);

                int bglob = bg * 32 + bp + c * 8;
                g_hbuf[(t + 1) & 1][bglob * Hsz + j] = hn;
                g_hs[(size_t)(bglob * Ssz + t) * Hsz + j] = hn;
            }
        }

        // ---- grid barrier (unchanged, measured-best flavor) ----
        __threadfence();
        __syncthreads();
        if (tid == 0) {
            unsigned target = (unsigned)NBLK * (unsigned)(t + 1);
            unsigned prev = atomicAdd(&g_count, 1u);
            if (prev + 1u == target) {
                atomicExch(&g_gen, (unsigned)(t + 1));
            } else {
                long long spins = 0;
                while (ld_acq(&g_gen) < (unsigned)(t + 1)) {
                    __nanosleep(64);
                    if (++spins > 100000000LL) break;
                }
            }
        }
        __syncthreads();
    }

    if (ks == 0) {
        #pragma unroll
        for (int c = 0; c < 4; c++)
            g_c[(bg * 32 + bp + c * 8) * Hsz + j] = cst[c];
    }
}

// ---------------------------------------------------------------------------
// Launch 4: fused output head + final-state copy
// ---------------------------------------------------------------------------
__global__ void headfin_kernel(const float* __restrict__ Wfc, const float* __restrict__ bfc,
                               float* __restrict__ out) {
    const int blk = blockIdx.x;
    if (blk < 4096) {
        int warp = blk * 8 + ((int)threadIdx.x >> 5);
        int lane = threadIdx.x & 31;
        const float* hrow = &g_hs[(size_t)warp * Hsz];
        float acc = 0.0f;
        #pragma unroll
        for (int q = 0; q < 4; q++) {
            float4 h = *(const float4*)&hrow[q * 128 + lane * 4];
            float4 w = *(const float4*)&Wfc[q * 128 + lane * 4];
            acc += h.x * w.x + h.y * w.y + h.z * w.z + h.w * w.w;
        }
        #pragma unroll
        for (int s = 16; s > 0; s >>= 1) acc += __shfl_xor_sync(0xFFFFFFFFu, acc, s);
        if (lane == 0) out[warp] = acc + bfc[0];
    } else {
        int i = (blk - 4096) * 256 + threadIdx.x;
        #pragma unroll
        for (int r = 0; r < 2; r++) {
            int v = i * 2 + r;
            out[32768 + v] = g_hbuf[0][v];
            out[65536 + v] = g_c[v];
        }
    }
}

// ---------------------------------------------------------------------------
extern "C" void kernel_launch(void* const* d_in, const int* in_sizes, int n_in,
                              void* d_out, int out_size) {
    const float* x   = (const float*)d_in[0];
    const float* Wf  = (const float*)d_in[1];
    const float* Wi  = (const float*)d_in[2];
    const float* Wo  = (const float*)d_in[3];
    const float* Wc  = (const float*)d_in[4];
    const float* bf  = (const float*)d_in[5];
    const float* bi  = (const float*)d_in[6];
    const float* bo  = (const float*)d_in[7];
    const float* bc  = (const float*)d_in[8];
    const float* Uf  = (const float*)d_in[9];
    const float* Ui  = (const float*)d_in[10];
    const float* Uo  = (const float*)d_in[11];
    const float* Uc  = (const float*)d_in[12];
    const float* Wfc = (const float*)d_in[13];
    const float* bfc = (const float*)d_in[14];
    float* out = (float*)d_out;

    cudaFuncSetAttribute(recur_kernel, cudaFuncAttributeMaxDynamicSharedMemorySize, RECUR_SMEM);
    cudaFuncSetAttribute(gemm_tc_kernel, cudaFuncAttributeMaxDynamicSharedMemorySize, GT_SMEM);

    splitx_kernel<<<ROWS * Dsz / 256, 256>>>(x);                       // launch 0
    prep_kernel<<<4224, 256>>>(Wf, Wi, Wo, Wc, bf, bi, bo, bc,
                               Uf, Ui, Uo, Uc);                        // launch 1
    gemm_tc_kernel<<<dim3(GXN / 64, ROWS / 128), 256, GT_SMEM>>>();    // launch 2
    recur_kernel<<<NBLK, 512, RECUR_SMEM>>>();                         // launch 3 (profiled)
    headfin_kernel<<<4096 + 64, 256>>>(Wfc, bfc, out);                 // launch 4
}

// round 14
// speedup vs baseline: 2.4360x; 1.2739x over previous
#include <cuda_runtime.h>
#include <cuda_bf16.h>

typedef unsigned long long ull;

#define Bsz 64
#define Ssz 512
#define Dsz 256
#define Hsz 512
#define ROWS (Bsz * Ssz)   /* 32768 */
#define GXN  (4 * Hsz)     /* 2048  */
#define NBLK 128           /* persistent CTAs (all resident on 148 SMs) */

// ---------------------------------------------------------------------------
// Static device scratch
// ---------------------------------------------------------------------------
__device__ float g_gxq[(size_t)ROWS * GXN];   // [b*512+t][j*4+gate]
__device__ float g_hs[(size_t)ROWS * Hsz];    // [b*512+t][j]
__device__ float g_c[Bsz * Hsz];
__device__ float g_bq[GXN];
__device__ unsigned g_count;
__device__ unsigned g_gen;
// bf16 split operands for the tensor-core input GEMM
__device__ __nv_bfloat16 g_xhi[(size_t)ROWS * Dsz];
__device__ __nv_bfloat16 g_xlo[(size_t)ROWS * Dsz];
__device__ __nv_bfloat16 g_Wthi[(size_t)GXN * Dsz];   // [n][k] (n = j*4+gate)
__device__ __nv_bfloat16 g_Wtlo[(size_t)GXN * Dsz];
// bf16 split U for the HMMA recurrence: [jg(64)][n32(32)][k(512)], n32 = j8*4+g
__device__ __nv_bfloat16 g_Ubhi[64 * 32 * 512];
__device__ __nv_bfloat16 g_Ublo[64 * 32 * 512];
// bf16 split h, double-buffered: [buf][b(64)][j(512)]
__device__ __nv_bfloat16 g_hbhi[2][Bsz * Hsz];
__device__ __nv_bfloat16 g_hblo[2][Bsz * Hsz];

// ---------------------------------------------------------------------------
// helpers
// ---------------------------------------------------------------------------
__device__ __forceinline__ unsigned ld_acq(const unsigned* p) {
    unsigned v; asm volatile("ld.acquire.gpu.b32 %0, [%1];" : "=r"(v) : "l"(p)); return v;
}
__device__ __forceinline__ float sigmoidf_(float x) { return 1.0f / (1.0f + __expf(-x)); }
__device__ __forceinline__ float tanhf_(float x)    { return 1.0f - 2.0f / (__expf(2.0f * x) + 1.0f); }

__device__ __forceinline__ unsigned smem_u32(const void* p) {
    unsigned a;
    asm("{ .reg .u64 t; cvta.to.shared.u64 t, %1; cvt.u32.u64 %0, t; }" : "=r"(a) : "l"(p));
    return a;
}
__device__ __forceinline__ void ldsm4(unsigned& r0, unsigned& r1, unsigned& r2, unsigned& r3,
                                      unsigned addr) {
    asm volatile("ldmatrix.sync.aligned.m8n8.x4.shared.b16 {%0,%1,%2,%3}, [%4];"
                 : "=r"(r0), "=r"(r1), "=r"(r2), "=r"(r3) : "r"(addr));
}
__device__ __forceinline__ void ldsm2(unsigned& r0, unsigned& r1, unsigned addr) {
    asm volatile("ldmatrix.sync.aligned.m8n8.x2.shared.b16 {%0,%1}, [%2];"
                 : "=r"(r0), "=r"(r1) : "r"(addr));
}
__device__ __forceinline__ void mma_bf16(float& c0, float& c1, float& c2, float& c3,
                                         unsigned a0, unsigned a1, unsigned a2, unsigned a3,
                                         unsigned b0, unsigned b1) {
    asm volatile("mma.sync.aligned.m16n8k16.row.col.f32.bf16.bf16.f32 "
                 "{%0,%1,%2,%3}, {%4,%5,%6,%7}, {%8,%9}, {%0,%1,%2,%3};"
                 : "+f"(c0), "+f"(c1), "+f"(c2), "+f"(c3)
                 : "r"(a0), "r"(a1), "r"(a2), "r"(a3), "r"(b0), "r"(b1));
}

// ---------------------------------------------------------------------------
// Launch 0: split x into bf16 hi/lo
// ---------------------------------------------------------------------------
__global__ void splitx_kernel(const float* __restrict__ x) {
    size_t i = (size_t)blockIdx.x * blockDim.x + threadIdx.x;   // ROWS*Dsz
    float v = x[i];
    __nv_bfloat16 hi = __float2bfloat16(v);
    g_xhi[i] = hi;
    g_xlo[i] = __float2bfloat16(v - __bfloat162float(hi));
}

// ---------------------------------------------------------------------------
// Launch 1: fused prep
//   blocks [0,4096):      U -> bf16 hi/lo [jg][n32][k]
//   blocks [4096,6144):   W -> transposed bf16 hi/lo + bias
//   blocks [6144,6400):   zero h0 (bf16 bufs) + counters
// ---------------------------------------------------------------------------
__global__ void prep_kernel(const float* __restrict__ Wf, const float* __restrict__ Wi,
                            const float* __restrict__ Wo, const float* __restrict__ Wc,
                            const float* __restrict__ bf, const float* __restrict__ bi,
                            const float* __restrict__ bo, const float* __restrict__ bc,
                            const float* __restrict__ Uf, const float* __restrict__ Ui,
                            const float* __restrict__ Uo, const float* __restrict__ Uc) {
    const int blk = blockIdx.x;
    const int tid = threadIdx.x;
    if (blk < 4096) {
        int idx = blk * 256 + tid;                 // 0..1048575 = jg*32n*512k
        int k   = idx & 511;
        int n32 = (idx >> 9) & 31;
        int jg  = idx >> 14;
        int j   = jg * 8 + (n32 >> 2);
        int g   = n32 & 3;
        const float* Ug = (g == 0) ? Uf : (g == 1) ? Ui : (g == 2) ? Uo : Uc;
        float v = Ug[(size_t)k * Hsz + j];
        __nv_bfloat16 hi = __float2bfloat16(v);
        g_Ubhi[idx] = hi;
        g_Ublo[idx] = __float2bfloat16(v - __bfloat162float(hi));
    } else if (blk < 6144) {
        int idx = (blk - 4096) * 256 + tid;        // 0..524287
        int n = idx >> 8;
        int k = idx & 255;
        int j = n >> 2, g = n & 3;
        const float* Wg = (g == 0) ? Wf : (g == 1) ? Wi : (g == 2) ? Wo : Wc;
        float v = Wg[(size_t)k * Hsz + j];
        __nv_bfloat16 hi = __float2bfloat16(v);
        g_Wthi[(size_t)n * Dsz + k] = hi;
        g_Wtlo[(size_t)n * Dsz + k] = __float2bfloat16(v - __bfloat162float(hi));
        if (k == 0) {
            const float* bg = (g == 0) ? bf : (g == 1) ? bi : (g == 2) ? bo : bc;
            g_bq[n] = bg[j];
        }
    } else {
        int i = (blk - 6144) * 256 + tid;          // 0..65535
        if (i < Bsz * Hsz) {
            g_hbhi[0][i] = __float2bfloat16(0.0f);
            g_hblo[0][i] = __float2bfloat16(0.0f);
        }
        if (i == 0) { g_count = 0u; g_gen = 0u; }
    }
}

// ---------------------------------------------------------------------------
// Launch 2: mma.sync bf16 split-precision input GEMM (unchanged, measured good)
// ---------------------------------------------------------------------------
#define SB_ST   264
#define SA_ST   40
#define SB_HI   0
#define SB_LO   (64 * SB_ST * 2)
#define SA_HI   (2 * 64 * SB_ST * 2)
#define SA_LO   (SA_HI + 128 * SA_ST * 2)
#define GT_SMEM (SA_LO + 128 * SA_ST * 2)     /* 88064 */

__global__ void __launch_bounds__(256, 2)
gemm_tc_kernel() {
    extern __shared__ char smem[];
    const unsigned sbase = smem_u32(smem);

    const int tid  = threadIdx.x;
    const int lane = tid & 31;
    const int wid  = tid >> 5;
    const int wm   = wid & 3;
    const int wn   = wid >> 2;
    const int m0w  = wm * 32;
    const int n0w  = wn * 32;
    const int n0   = blockIdx.x * 64;
    const int r0   = blockIdx.y * 128;

    #pragma unroll
    for (int r = 0; r < 8; r++) {
        int v = r * 256 + tid;
        int row = v >> 5, cu = v & 31;
        size_t src = (size_t)(n0 + row) * Dsz + cu * 8;
        *(uint4*)(smem + SB_HI + (row * SB_ST + cu * 8) * 2) = *(const uint4*)&g_Wthi[src];
        *(uint4*)(smem + SB_LO + (row * SB_ST + cu * 8) * 2) = *(const uint4*)&g_Wtlo[src];
    }

    float c[2][4][4];
    #pragma unroll
    for (int mi = 0; mi < 2; mi++)
        #pragma unroll
        for (int ni = 0; ni < 4; ni++)
            #pragma unroll
            for (int e = 0; e < 4; e++) c[mi][ni][e] = 0.0f;

    const int aRow  = lane & 15;
    const int aKoff = (lane >> 4) * 8;
    const int bSel  = lane >> 3;
    const int bRow  = (bSel >> 1) * 8 + (lane & 7);
    const int bKoff = (bSel & 1) * 8;

    for (int kc = 0; kc < 8; kc++) {
        __syncthreads();
        #pragma unroll
        for (int r = 0; r < 2; r++) {
            int v = r * 256 + tid;
            int row = v >> 2, cu = v & 3;
            size_t src = (size_t)(r0 + row) * Dsz + kc * 32 + cu * 8;
            *(uint4*)(smem + SA_HI + (row * SA_ST + cu * 8) * 2) = *(const uint4*)&g_xhi[src];
            *(uint4*)(smem + SA_LO + (row * SA_ST + cu * 8) * 2) = *(const uint4*)&g_xlo[src];
        }
        __syncthreads();

        #pragma unroll
        for (int ks = 0; ks < 2; ks++) {
            const int kchunk = ks * 16;
            const int kglob  = kc * 32 + kchunk;

            unsigned ah[2][4], al[2][4];
            #pragma unroll
            for (int mi = 0; mi < 2; mi++) {
                unsigned off = (unsigned)((m0w + mi * 16 + aRow) * SA_ST + kchunk + aKoff) * 2;
                ldsm4(ah[mi][0], ah[mi][1], ah[mi][2], ah[mi][3], sbase + SA_HI + off);
                ldsm4(al[mi][0], al[mi][1], al[mi][2], al[mi][3], sbase + SA_LO + off);
            }
            unsigned bh[4][2], bl[4][2];
            #pragma unroll
            for (int half = 0; half < 2; half++) {
                unsigned off = (unsigned)((n0w + half * 16 + bRow) * SB_ST + kglob + bKoff) * 2;
                ldsm4(bh[half * 2][0], bh[half * 2][1], bh[half * 2 + 1][0], bh[half * 2 + 1][1],
                      sbase + SB_HI + off);
                ldsm4(bl[half * 2][0], bl[half * 2][1], bl[half * 2 + 1][0], bl[half * 2 + 1][1],
                      sbase + SB_LO + off);
            }

            #pragma unroll
            for (int mi = 0; mi < 2; mi++)
                #pragma unroll
                for (int ni = 0; ni < 4; ni++) {
                    float* cc = c[mi][ni];
                    mma_bf16(cc[0], cc[1], cc[2], cc[3],
                             ah[mi][0], ah[mi][1], ah[mi][2], ah[mi][3],
                             bh[ni][0], bh[ni][1]);
                    mma_bf16(cc[0], cc[1], cc[2], cc[3],
                             ah[mi][0], ah[mi][1], ah[mi][2], ah[mi][3],
                             bl[ni][0], bl[ni][1]);
                    mma_bf16(cc[0], cc[1], cc[2], cc[3],
                             al[mi][0], al[mi][1], al[mi][2], al[mi][3],
                             bh[ni][0], bh[ni][1]);
                }
        }
    }

    const int crow = lane >> 2;
    const int ccol = (lane & 3) * 2;
    #pragma unroll
    for (int mi = 0; mi < 2; mi++) {
        #pragma unroll
        for (int ni = 0; ni < 4; ni++) {
            int col = n0 + n0w + ni * 8 + ccol;
            float2 bb = *(const float2*)&g_bq[col];
            int m1 = r0 + m0w + mi * 16 + crow;
            float2 o0; o0.x = c[mi][ni][0] + bb.x; o0.y = c[mi][ni][1] + bb.y;
            float2 o1; o1.x = c[mi][ni][2] + bb.x; o1.y = c[mi][ni][3] + bb.y;
            *(float2*)&g_gxq[(size_t)m1 * GXN + col] = o0;
            *(float2*)&g_gxq[(size_t)(m1 + 8) * GXN + col] = o1;
        }
    }
}

// ---------------------------------------------------------------------------
// Launch 3 (PROFILED): persistent HMMA LSTM recurrence
//   128 CTAs = 64 jg x 2 bg. Per CTA/step: [32b x 32n x 512k] split-bf16 mma.
//   16 warps = 4 n-groups (8 n) x 4 k-slices (128 k). 48 mma/warp/step.
//   SMEM: sU [2][32n][520] bf16 ; sH [2][32b][520] bf16 ;
//         sRed [4][32][34] f32 (EVEN stride -> aligned float2).
// ---------------------------------------------------------------------------
#define RN_ST    520                     /* bf16 per row (1040B stride) */
#define RN_SPLIT (32 * RN_ST * 2)        /* 33280 B per split */
#define RN_SU    0
#define RN_SH    (2 * RN_SPLIT)          /* 66560 */
#define RN_SRED  (4 * RN_SPLIT)          /* 133120 */
#define RN_RST   34                      /* f32 stride per m-row (even!) */
#define RN_RSL   (32 * RN_RST)           /* 1088 floats per k-slice */
#define RN_SMEM  (RN_SRED + 4 * RN_RSL * 4)    /* 150528 */

__global__ void __launch_bounds__(512, 1)
recur_kernel() {
    extern __shared__ char smem[];
    const unsigned sbase = smem_u32(smem);
    float* sRedF = (float*)(smem + RN_SRED);

    const int tid  = threadIdx.x;
    const int lane = tid & 31;
    const int wid  = tid >> 5;
    const int ng   = wid & 3;            // n-group (8 n cols)
    const int ksl  = wid >> 2;           // k-slice (128 k)
    const int jg   = blockIdx.x >> 1;
    const int bg   = blockIdx.x & 1;

    // ---- load U slice (bf16 hi/lo) into SMEM once ----
    {
        const __nv_bfloat16* uh = &g_Ubhi[jg * 32 * 512];
        const __nv_bfloat16* ul = &g_Ublo[jg * 32 * 512];
        #pragma unroll
        for (int r = 0; r < 8; r++) {
            int v = r * 512 + tid;               // 0..4095 uint4 (both splits)
            int split = v >> 11;
            int w = v & 2047;
            int n = w >> 6, k8 = w & 63;
            const __nv_bfloat16* src = split ? ul : uh;
            *(uint4*)(smem + RN_SU + split * RN_SPLIT + n * (RN_ST * 2) + k8 * 16) =
                *(const uint4*)&src[n * 512 + k8 * 8];
        }
    }

    // ldmatrix lane addressing
    const int aRow  = lane & 15;
    const int aKoff = (lane >> 4) * 8;
    const int bRow  = lane & 7;
    const int bKoff = ((lane >> 3) & 1) * 8;

    // epilogue cell ownership (tid < 256): b = tid&31, j8 = tid>>5
    const int eb  = tid & 31;
    const int ej8 = (tid >> 5) & 7;
    const int ejcol = jg * 8 + ej8;
    float cst = 0.0f;

    for (int t = 0; t < Ssz; t++) {
        const int rd = t & 1, wr = rd ^ 1;

        // gx prefetch (epilogue threads)
        float4 gx;
        if (tid < 256)
            gx = *(const float4*)
                &g_gxq[(size_t)((bg * 32 + eb) * Ssz + t) * GXN + ejcol * 4];

        // ---- stage h (bf16 hi/lo) rows [bg*32, bg*32+32) ----
        {
            const __nv_bfloat16* hh = g_hbhi[rd];
            const __nv_bfloat16* hl = g_hblo[rd];
            #pragma unroll
            for (int r = 0; r < 8; r++) {
                int v = r * 512 + tid;           // 0..4095 uint4 (both splits)
                int split = v >> 11;
                int w = v & 2047;
                int row = w >> 6, k8 = w & 63;
                const __nv_bfloat16* src = split ? hl : hh;
                uint4 d = __ldcg((const uint4*)&src[(bg * 32 + row) * Hsz + k8 * 8]);
                *(uint4*)(smem + RN_SH + split * RN_SPLIT + row * (RN_ST * 2) + k8 * 16) = d;
            }
        }
        __syncthreads();

        // ---- HMMA compute: per warp 8 k-frags x (2 m-frags x 3 products) ----
        float c[2][4];
        #pragma unroll
        for (int mi = 0; mi < 2; mi++)
            #pragma unroll
            for (int e = 0; e < 4; e++) c[mi][e] = 0.0f;

        const int kbase = ksl * 128;
        #pragma unroll 2
        for (int kf = 0; kf < 8; kf++) {
            const int k = kbase + kf * 16;
            unsigned ah[2][4], al[2][4];
            #pragma unroll
            for (int mi = 0; mi < 2; mi++) {
                unsigned off = (unsigned)((mi * 16 + aRow) * (RN_ST * 2) + (k + aKoff) * 2);
                ldsm4(ah[mi][0], ah[mi][1], ah[mi][2], ah[mi][3],
                      sbase + RN_SH + off);
                ldsm4(al[mi][0], al[mi][1], al[mi][2], al[mi][3],
                      sbase + RN_SH + RN_SPLIT + off);
            }
            unsigned bh[2], bl[2];
            {
                unsigned off = (unsigned)((ng * 8 + bRow) * (RN_ST * 2) + (k + bKoff) * 2);
                ldsm2(bh[0], bh[1], sbase + RN_SU + off);
                ldsm2(bl[0], bl[1], sbase + RN_SU + RN_SPLIT + off);
            }
            #pragma unroll
            for (int mi = 0; mi < 2; mi++) {
                mma_bf16(c[mi][0], c[mi][1], c[mi][2], c[mi][3],
                         ah[mi][0], ah[mi][1], ah[mi][2], ah[mi][3], bh[0], bh[1]);
                mma_bf16(c[mi][0], c[mi][1], c[mi][2], c[mi][3],
                         ah[mi][0], ah[mi][1], ah[mi][2], ah[mi][3], bl[0], bl[1]);
                mma_bf16(c[mi][0], c[mi][1], c[mi][2], c[mi][3],
                         al[mi][0], al[mi][1], al[mi][2], al[mi][3], bh[0], bh[1]);
            }
        }

        // ---- write partials to sRed[ksl][m][RN_RST] (even stride, aligned) ----
        {
            const int col = ng * 8 + (lane & 3) * 2;
            #pragma unroll
            for (int mi = 0; mi < 2; mi++) {
                int m = mi * 16 + (lane >> 2);
                float2 p0; p0.x = c[mi][0]; p0.y = c[mi][1];
                float2 p1; p1.x = c[mi][2]; p1.y = c[mi][3];
                *(float2*)&sRedF[ksl * RN_RSL + m * RN_RST + col]       = p0;
                *(float2*)&sRedF[ksl * RN_RSL + (m + 8) * RN_RST + col] = p1;
            }
        }
        __syncthreads();

        // ---- epilogue: 256 threads, one (b,j) cell each ----
        if (tid < 256) {
            float s[4];
            #pragma unroll
            for (int g = 0; g < 4; g++) {
                int cix = eb * RN_RST + ej8 * 4 + g;
                s[g] = sRedF[cix] + sRedF[RN_RSL + cix]
                     + sRedF[2 * RN_RSL + cix] + sRedF[3 * RN_RSL + cix];
            }
            float pf = gx.x + s[0];
            float pi = gx.y + s[1];
            float po = gx.z + s[2];
            float pc = gx.w + s[3];

            cst = sigmoidf_(pf) * cst + sigmoidf_(pi) * tanhf_(pc);
            float hn = sigmoidf_(po) * tanhf_(cst);

            int bglob = bg * 32 + eb;
            __nv_bfloat16 hhi = __float2bfloat16(hn);
            g_hbhi[wr][bglob * Hsz + ejcol] = hhi;
            g_hblo[wr][bglob * Hsz + ejcol] =
                __float2bfloat16(hn - __bfloat162float(hhi));
            g_hs[(size_t)(bglob * Ssz + t) * Hsz + ejcol] = hn;
        }

        // ---- grid barrier (measured-best flavor) ----
        __threadfence();
        __syncthreads();
        if (tid == 0) {
            unsigned target = (unsigned)NBLK * (unsigned)(t + 1);
            unsigned prev = atomicAdd(&g_count, 1u);
            if (prev + 1u == target) {
                atomicExch(&g_gen, (unsigned)(t + 1));
            } else {
                long long spins = 0;
                while (ld_acq(&g_gen) < (unsigned)(t + 1)) {
                    __nanosleep(64);
                    if (++spins > 100000000LL) break;
                }
            }
        }
        __syncthreads();
    }

    if (tid < 256)
        g_c[(bg * 32 + eb) * Hsz + ejcol] = cst;
}

// ---------------------------------------------------------------------------
// Launch 4: fused output head + final-state copy (h_t taken from g_hs[:,511])
// ---------------------------------------------------------------------------
__global__ void headfin_kernel(const float* __restrict__ Wfc, const float* __restrict__ bfc,
                               float* __restrict__ out) {
    const int blk = blockIdx.x;
    if (blk < 4096) {
        int warp = blk * 8 + ((int)threadIdx.x >> 5);
        int lane = threadIdx.x & 31;
        const float* hrow = &g_hs[(size_t)warp * Hsz];
        float acc = 0.0f;
        #pragma unroll
        for (int q = 0; q < 4; q++) {
            float4 h = *(const float4*)&hrow[q * 128 + lane * 4];
            float4 w = *(const float4*)&Wfc[q * 128 + lane * 4];
            acc += h.x * w.x + h.y * w.y + h.z * w.z + h.w * w.w;
        }
        #pragma unroll
        for (int s = 16; s > 0; s >>= 1) acc += __shfl_xor_sync(0xFFFFFFFFu, acc, s);
        if (lane == 0) out[warp] = acc + bfc[0];
    } else {
        int i = (blk - 4096) * 256 + threadIdx.x;
        #pragma unroll
        for (int r = 0; r < 2; r++) {
            int v = i * 2 + r;                  // 0..32767 = b*512 + j
            int b = v >> 9, j = v & 511;
            out[32768 + v] = g_hs[(size_t)(b * Ssz + 511) * Hsz + j];
            out[65536 + v] = g_c[v];
        }
    }
}

// ---------------------------------------------------------------------------
extern "C" void kernel_launch(void* const* d_in, const int* in_sizes, int n_in,
                              void* d_out, int out_size) {
    const float* x   = (const float*)d_in[0];
    const float* Wf  = (const float*)d_in[1];
    const float* Wi  = (const float*)d_in[2];
    const float* Wo  = (const float*)d_in[3];
    const float* Wc  = (const float*)d_in[4];
    const float* bf  = (const float*)d_in[5];
    const float* bi  = (const float*)d_in[6];
    const float* bo  = (const float*)d_in[7];
    const float* bc  = (const float*)d_in[8];
    const float* Uf  = (const float*)d_in[9];
    const float* Ui  = (const float*)d_in[10];
    const float* Uo  = (const float*)d_in[11];
    const float* Uc  = (const float*)d_in[12];
    const float* Wfc = (const float*)d_in[13];
    const float* bfc = (const float*)d_in[14];
    float* out = (float*)d_out;

    cudaFuncSetAttribute(recur_kernel, cudaFuncAttributeMaxDynamicSharedMemorySize, RN_SMEM);
    cudaFuncSetAttribute(gemm_tc_kernel, cudaFuncAttributeMaxDynamicSharedMemorySize, GT_SMEM);

    splitx_kernel<<<ROWS * Dsz / 256, 256>>>(x);                       // launch 0
    prep_kernel<<<6400, 256>>>(Wf, Wi, Wo, Wc, bf, bi, bo, bc,
                               Uf, Ui, Uo, Uc);                        // launch 1
    gemm_tc_kernel<<<dim3(GXN / 64, ROWS / 128), 256, GT_SMEM>>>();    // launch 2
    recur_kernel<<<NBLK, 512, RN_SMEM>>>();                            // launch 3 (profiled)
    headfin_kernel<<<4096 + 64, 256>>>(Wfc, bfc, out);                 // launch 4
}

// round 15
// speedup vs baseline: 2.4897x; 1.0220x over previous
#include <cuda_runtime.h>
#include <cuda_bf16.h>

typedef unsigned long long ull;

#define Bsz 64
#define Ssz 512
#define Dsz 256
#define Hsz 512
#define ROWS (Bsz * Ssz)   /* 32768 */
#define GXN  (4 * Hsz)     /* 2048  */
#define NBLK 128           /* persistent CTAs (all resident on 148 SMs) */

// ---------------------------------------------------------------------------
// Static device scratch
// ---------------------------------------------------------------------------
__device__ float g_gxq[(size_t)ROWS * GXN];   // [b*512+t][j*4+gate]
__device__ float g_hs[(size_t)ROWS * Hsz];    // [b*512+t][j]
__device__ float g_c[Bsz * Hsz];
__device__ float g_bq[GXN];
// per-bgroup barrier state (separate 128B lines)
__device__ unsigned g_cnt2[2 * 32];
__device__ unsigned g_gen2[2 * 32];
// bf16 split operands for the tensor-core input GEMM (W only; x converted in-kernel)
__device__ __nv_bfloat16 g_Wthi[(size_t)GXN * Dsz];   // [n][k] (n = j*4+gate)
__device__ __nv_bfloat16 g_Wtlo[(size_t)GXN * Dsz];
// bf16 split U for the HMMA recurrence: [jg(64)][n32(32)][k(512)], n32 = j8*4+g
__device__ __nv_bfloat16 g_Ubhi[64 * 32 * 512];
__device__ __nv_bfloat16 g_Ublo[64 * 32 * 512];
// bf16 split h, double-buffered: [buf][b(64)][j(512)]
__device__ __nv_bfloat16 g_hbhi[2][Bsz * Hsz];
__device__ __nv_bfloat16 g_hblo[2][Bsz * Hsz];

// ---------------------------------------------------------------------------
// helpers
// ---------------------------------------------------------------------------
__device__ __forceinline__ unsigned ld_acq(const unsigned* p) {
    unsigned v; asm volatile("ld.acquire.gpu.b32 %0, [%1];" : "=r"(v) : "l"(p)); return v;
}
__device__ __forceinline__ float sigmoidf_(float x) { return 1.0f / (1.0f + __expf(-x)); }
__device__ __forceinline__ float tanhf_(float x)    { return 1.0f - 2.0f / (__expf(2.0f * x) + 1.0f); }

__device__ __forceinline__ unsigned smem_u32(const void* p) {
    unsigned a;
    asm("{ .reg .u64 t; cvta.to.shared.u64 t, %1; cvt.u32.u64 %0, t; }" : "=r"(a) : "l"(p));
    return a;
}
__device__ __forceinline__ void ldsm4(unsigned& r0, unsigned& r1, unsigned& r2, unsigned& r3,
                                      unsigned addr) {
    asm volatile("ldmatrix.sync.aligned.m8n8.x4.shared.b16 {%0,%1,%2,%3}, [%4];"
                 : "=r"(r0), "=r"(r1), "=r"(r2), "=r"(r3) : "r"(addr));
}
__device__ __forceinline__ void ldsm2(unsigned& r0, unsigned& r1, unsigned addr) {
    asm volatile("ldmatrix.sync.aligned.m8n8.x2.shared.b16 {%0,%1}, [%2];"
                 : "=r"(r0), "=r"(r1) : "r"(addr));
}
__device__ __forceinline__ void mma_bf16(float& c0, float& c1, float& c2, float& c3,
                                         unsigned a0, unsigned a1, unsigned a2, unsigned a3,
                                         unsigned b0, unsigned b1) {
    asm volatile("mma.sync.aligned.m16n8k16.row.col.f32.bf16.bf16.f32 "
                 "{%0,%1,%2,%3}, {%4,%5,%6,%7}, {%8,%9}, {%0,%1,%2,%3};"
                 : "+f"(c0), "+f"(c1), "+f"(c2), "+f"(c3)
                 : "r"(a0), "r"(a1), "r"(a2), "r"(a3), "r"(b0), "r"(b1));
}

// ---------------------------------------------------------------------------
// Launch 0: init — zero h0 (bf16 bufs) + barrier counters
// ---------------------------------------------------------------------------
__global__ void init_kernel() {
    int i = blockIdx.x * blockDim.x + threadIdx.x;     // 0..32767
    g_hbhi[0][i] = __float2bfloat16(0.0f);
    g_hblo[0][i] = __float2bfloat16(0.0f);
    if (i < 2) { g_cnt2[i * 32] = 0u; g_gen2[i * 32] = 0u; }
}

// ---------------------------------------------------------------------------
// Launch 1: fused prep
//   blocks [0,4096):      U -> bf16 hi/lo [jg][n32][k]
//   blocks [4096,6144):   W -> transposed bf16 hi/lo + bias
// ---------------------------------------------------------------------------
__global__ void prep_kernel(const float* __restrict__ Wf, const float* __restrict__ Wi,
                            const float* __restrict__ Wo, const float* __restrict__ Wc,
                            const float* __restrict__ bf, const float* __restrict__ bi,
                            const float* __restrict__ bo, const float* __restrict__ bc,
                            const float* __restrict__ Uf, const float* __restrict__ Ui,
                            const float* __restrict__ Uo, const float* __restrict__ Uc) {
    const int blk = blockIdx.x;
    const int tid = threadIdx.x;
    if (blk < 4096) {
        int idx = blk * 256 + tid;                 // 0..1048575 = jg*32n*512k
        int k   = idx & 511;
        int n32 = (idx >> 9) & 31;
        int jg  = idx >> 14;
        int j   = jg * 8 + (n32 >> 2);
        int g   = n32 & 3;
        const float* Ug = (g == 0) ? Uf : (g == 1) ? Ui : (g == 2) ? Uo : Uc;
        float v = Ug[(size_t)k * Hsz + j];
        __nv_bfloat16 hi = __float2bfloat16(v);
        g_Ubhi[idx] = hi;
        g_Ublo[idx] = __float2bfloat16(v - __bfloat162float(hi));
    } else {
        int idx = (blk - 4096) * 256 + tid;        // 0..524287
        int n = idx >> 8;
        int k = idx & 255;
        int j = n >> 2, g = n & 3;
        const float* Wg = (g == 0) ? Wf : (g == 1) ? Wi : (g == 2) ? Wo : Wc;
        float v = Wg[(size_t)k * Hsz + j];
        __nv_bfloat16 hi = __float2bfloat16(v);
        g_Wthi[(size_t)n * Dsz + k] = hi;
        g_Wtlo[(size_t)n * Dsz + k] = __float2bfloat16(v - __bfloat162float(hi));
        if (k == 0) {
            const float* bg = (g == 0) ? bf : (g == 1) ? bi : (g == 2) ? bo : bc;
            g_bq[n] = bg[j];
        }
    }
}

// ---------------------------------------------------------------------------
// Launch 2: mma.sync bf16 split-precision input GEMM
//   (x loaded as fp32 and split to hi/lo in-register — splitx kernel fused away)
// ---------------------------------------------------------------------------
#define SB_ST   264
#define SA_ST   40
#define SB_HI   0
#define SB_LO   (64 * SB_ST * 2)
#define SA_HI   (2 * 64 * SB_ST * 2)
#define SA_LO   (SA_HI + 128 * SA_ST * 2)
#define GT_SMEM (SA_LO + 128 * SA_ST * 2)     /* 88064 */

__global__ void __launch_bounds__(256, 2)
gemm_tc_kernel(const float* __restrict__ x) {
    extern __shared__ char smem[];
    const unsigned sbase = smem_u32(smem);

    const int tid  = threadIdx.x;
    const int lane = tid & 31;
    const int wid  = tid >> 5;
    const int wm   = wid & 3;
    const int wn   = wid >> 2;
    const int m0w  = wm * 32;
    const int n0w  = wn * 32;
    const int n0   = blockIdx.x * 64;
    const int r0   = blockIdx.y * 128;

    #pragma unroll
    for (int r = 0; r < 8; r++) {
        int v = r * 256 + tid;
        int row = v >> 5, cu = v & 31;
        size_t src = (size_t)(n0 + row) * Dsz + cu * 8;
        *(uint4*)(smem + SB_HI + (row * SB_ST + cu * 8) * 2) = *(const uint4*)&g_Wthi[src];
        *(uint4*)(smem + SB_LO + (row * SB_ST + cu * 8) * 2) = *(const uint4*)&g_Wtlo[src];
    }

    float c[2][4][4];
    #pragma unroll
    for (int mi = 0; mi < 2; mi++)
        #pragma unroll
        for (int ni = 0; ni < 4; ni++)
            #pragma unroll
            for (int e = 0; e < 4; e++) c[mi][ni][e] = 0.0f;

    const int aRow  = lane & 15;
    const int aKoff = (lane >> 4) * 8;
    const int bSel  = lane >> 3;
    const int bRow  = (bSel >> 1) * 8 + (lane & 7);
    const int bKoff = (bSel & 1) * 8;

    for (int kc = 0; kc < 8; kc++) {
        __syncthreads();
        #pragma unroll
        for (int r = 0; r < 2; r++) {
            int v = r * 256 + tid;
            int row = v >> 2, cu = v & 3;
            const float* src = &x[(size_t)(r0 + row) * Dsz + kc * 32 + cu * 8];
            float4 f0 = *(const float4*)src;
            float4 f1 = *(const float4*)(src + 4);
            float vals[8] = {f0.x, f0.y, f0.z, f0.w, f1.x, f1.y, f1.z, f1.w};
            __nv_bfloat16 his[8], los[8];
            #pragma unroll
            for (int e = 0; e < 8; e++) {
                __nv_bfloat16 h = __float2bfloat16(vals[e]);
                his[e] = h;
                los[e] = __float2bfloat16(vals[e] - __bfloat162float(h));
            }
            *(uint4*)(smem + SA_HI + (row * SA_ST + cu * 8) * 2) = *(uint4*)his;
            *(uint4*)(smem + SA_LO + (row * SA_ST + cu * 8) * 2) = *(uint4*)los;
        }
        __syncthreads();

        #pragma unroll
        for (int ks = 0; ks < 2; ks++) {
            const int kchunk = ks * 16;
            const int kglob  = kc * 32 + kchunk;

            unsigned ah[2][4], al[2][4];
            #pragma unroll
            for (int mi = 0; mi < 2; mi++) {
                unsigned off = (unsigned)((m0w + mi * 16 + aRow) * SA_ST + kchunk + aKoff) * 2;
                ldsm4(ah[mi][0], ah[mi][1], ah[mi][2], ah[mi][3], sbase + SA_HI + off);
                ldsm4(al[mi][0], al[mi][1], al[mi][2], al[mi][3], sbase + SA_LO + off);
            }
            unsigned bh[4][2], bl[4][2];
            #pragma unroll
            for (int half = 0; half < 2; half++) {
                unsigned off = (unsigned)((n0w + half * 16 + bRow) * SB_ST + kglob + bKoff) * 2;
                ldsm4(bh[half * 2][0], bh[half * 2][1], bh[half * 2 + 1][0], bh[half * 2 + 1][1],
                      sbase + SB_HI + off);
                ldsm4(bl[half * 2][0], bl[half * 2][1], bl[half * 2 + 1][0], bl[half * 2 + 1][1],
                      sbase + SB_LO + off);
            }

            #pragma unroll
            for (int mi = 0; mi < 2; mi++)
                #pragma unroll
                for (int ni = 0; ni < 4; ni++) {
                    float* cc = c[mi][ni];
                    mma_bf16(cc[0], cc[1], cc[2], cc[3],
                             ah[mi][0], ah[mi][1], ah[mi][2], ah[mi][3],
                             bh[ni][0], bh[ni][1]);
                    mma_bf16(cc[0], cc[1], cc[2], cc[3],
                             ah[mi][0], ah[mi][1], ah[mi][2], ah[mi][3],
                             bl[ni][0], bl[ni][1]);
                    mma_bf16(cc[0], cc[1], cc[2], cc[3],
                             al[mi][0], al[mi][1], al[mi][2], al[mi][3],
                             bh[ni][0], bh[ni][1]);
                }
        }
    }

    const int crow = lane >> 2;
    const int ccol = (lane & 3) * 2;
    #pragma unroll
    for (int mi = 0; mi < 2; mi++) {
        #pragma unroll
        for (int ni = 0; ni < 4; ni++) {
            int col = n0 + n0w + ni * 8 + ccol;
            float2 bb = *(const float2*)&g_bq[col];
            int m1 = r0 + m0w + mi * 16 + crow;
            float2 o0; o0.x = c[mi][ni][0] + bb.x; o0.y = c[mi][ni][1] + bb.y;
            float2 o1; o1.x = c[mi][ni][2] + bb.x; o1.y = c[mi][ni][3] + bb.y;
            *(float2*)&g_gxq[(size_t)m1 * GXN + col] = o0;
            *(float2*)&g_gxq[(size_t)(m1 + 8) * GXN + col] = o1;
        }
    }
}

// ---------------------------------------------------------------------------
// Launch 3 (PROFILED): persistent HMMA LSTM recurrence
//   Barrier split per bgroup: 2 independent 64-CTA flat barriers (a CTA only
//   consumes its own bgroup's h rows). Fence only by storing threads.
// ---------------------------------------------------------------------------
#define RN_ST    520                     /* bf16 per row (1040B stride) */
#define RN_SPLIT (32 * RN_ST * 2)        /* 33280 B per split */
#define RN_SU    0
#define RN_SH    (2 * RN_SPLIT)          /* 66560 */
#define RN_SRED  (4 * RN_SPLIT)          /* 133120 */
#define RN_RST   34                      /* f32 stride per m-row (even) */
#define RN_RSL   (32 * RN_RST)           /* 1088 floats per k-slice */
#define RN_SMEM  (RN_SRED + 4 * RN_RSL * 4)    /* 150528 */

__global__ void __launch_bounds__(512, 1)
recur_kernel() {
    extern __shared__ char smem[];
    const unsigned sbase = smem_u32(smem);
    float* sRedF = (float*)(smem + RN_SRED);

    const int tid  = threadIdx.x;
    const int lane = tid & 31;
    const int wid  = tid >> 5;
    const int ng   = wid & 3;            // n-group (8 n cols)
    const int ksl  = wid >> 2;           // k-slice (128 k)
    const int jg   = blockIdx.x >> 1;
    const int bg   = blockIdx.x & 1;

    unsigned* cnt = &g_cnt2[bg * 32];
    unsigned* gen = &g_gen2[bg * 32];

    // ---- load U slice (bf16 hi/lo) into SMEM once ----
    {
        const __nv_bfloat16* uh = &g_Ubhi[jg * 32 * 512];
        const __nv_bfloat16* ul = &g_Ublo[jg * 32 * 512];
        #pragma unroll
        for (int r = 0; r < 8; r++) {
            int v = r * 512 + tid;               // 0..4095 uint4 (both splits)
            int split = v >> 11;
            int w = v & 2047;
            int n = w >> 6, k8 = w & 63;
            const __nv_bfloat16* src = split ? ul : uh;
            *(uint4*)(smem + RN_SU + split * RN_SPLIT + n * (RN_ST * 2) + k8 * 16) =
                *(const uint4*)&src[n * 512 + k8 * 8];
        }
    }

    const int aRow  = lane & 15;
    const int aKoff = (lane >> 4) * 8;
    const int bRow  = lane & 7;
    const int bKoff = ((lane >> 3) & 1) * 8;

    const int eb  = tid & 31;
    const int ej8 = (tid >> 5) & 7;
    const int ejcol = jg * 8 + ej8;
    float cst = 0.0f;

    for (int t = 0; t < Ssz; t++) {
        const int rd = t & 1, wr = rd ^ 1;

        float4 gx;
        if (tid < 256)
            gx = *(const float4*)
                &g_gxq[(size_t)((bg * 32 + eb) * Ssz + t) * GXN + ejcol * 4];

        // ---- stage h (bf16 hi/lo) rows [bg*32, bg*32+32) ----
        {
            const __nv_bfloat16* hh = g_hbhi[rd];
            const __nv_bfloat16* hl = g_hblo[rd];
            #pragma unroll
            for (int r = 0; r < 8; r++) {
                int v = r * 512 + tid;
                int split = v >> 11;
                int w = v & 2047;
                int row = w >> 6, k8 = w & 63;
                const __nv_bfloat16* src = split ? hl : hh;
                uint4 d = __ldcg((const uint4*)&src[(bg * 32 + row) * Hsz + k8 * 8]);
                *(uint4*)(smem + RN_SH + split * RN_SPLIT + row * (RN_ST * 2) + k8 * 16) = d;
            }
        }
        __syncthreads();

        // ---- HMMA compute ----
        float c[2][4];
        #pragma unroll
        for (int mi = 0; mi < 2; mi++)
            #pragma unroll
            for (int e = 0; e < 4; e++) c[mi][e] = 0.0f;

        const int kbase = ksl * 128;
        #pragma unroll 2
        for (int kf = 0; kf < 8; kf++) {
            const int k = kbase + kf * 16;
            unsigned ah[2][4], al[2][4];
            #pragma unroll
            for (int mi = 0; mi < 2; mi++) {
                unsigned off = (unsigned)((mi * 16 + aRow) * (RN_ST * 2) + (k + aKoff) * 2);
                ldsm4(ah[mi][0], ah[mi][1], ah[mi][2], ah[mi][3],
                      sbase + RN_SH + off);
                ldsm4(al[mi][0], al[mi][1], al[mi][2], al[mi][3],
                      sbase + RN_SH + RN_SPLIT + off);
            }
            unsigned bh[2], bl[2];
            {
                unsigned off = (unsigned)((ng * 8 + bRow) * (RN_ST * 2) + (k + bKoff) * 2);
                ldsm2(bh[0], bh[1], sbase + RN_SU + off);
                ldsm2(bl[0], bl[1], sbase + RN_SU + RN_SPLIT + off);
            }
            #pragma unroll
            for (int mi = 0; mi < 2; mi++) {
                mma_bf16(c[mi][0], c[mi][1], c[mi][2], c[mi][3],
                         ah[mi][0], ah[mi][1], ah[mi][2], ah[mi][3], bh[0], bh[1]);
                mma_bf16(c[mi][0], c[mi][1], c[mi][2], c[mi][3],
                         ah[mi][0], ah[mi][1], ah[mi][2], ah[mi][3], bl[0], bl[1]);
                mma_bf16(c[mi][0], c[mi][1], c[mi][2], c[mi][3],
                         al[mi][0], al[mi][1], al[mi][2], al[mi][3], bh[0], bh[1]);
            }
        }

        // ---- write partials to sRed[ksl][m][RN_RST] ----
        {
            const int col = ng * 8 + (lane & 3) * 2;
            #pragma unroll
            for (int mi = 0; mi < 2; mi++) {
                int m = mi * 16 + (lane >> 2);
                float2 p0; p0.x = c[mi][0]; p0.y = c[mi][1];
                float2 p1; p1.x = c[mi][2]; p1.y = c[mi][3];
                *(float2*)&sRedF[ksl * RN_RSL + m * RN_RST + col]       = p0;
                *(float2*)&sRedF[ksl * RN_RSL + (m + 8) * RN_RST + col] = p1;
            }
        }
        __syncthreads();

        // ---- epilogue: 256 threads, one (b,j) cell each ----
        if (tid < 256) {
            float s[4];
            #pragma unroll
            for (int g = 0; g < 4; g++) {
                int cix = eb * RN_RST + ej8 * 4 + g;
                s[g] = sRedF[cix] + sRedF[RN_RSL + cix]
                     + sRedF[2 * RN_RSL + cix] + sRedF[3 * RN_RSL + cix];
            }
            float pf = gx.x + s[0];
            float pi = gx.y + s[1];
            float po = gx.z + s[2];
            float pc = gx.w + s[3];

            cst = sigmoidf_(pf) * cst + sigmoidf_(pi) * tanhf_(pc);
            float hn = sigmoidf_(po) * tanhf_(cst);

            int bglob = bg * 32 + eb;
            __nv_bfloat16 hhi = __float2bfloat16(hn);
            g_hbhi[wr][bglob * Hsz + ejcol] = hhi;
            g_hblo[wr][bglob * Hsz + ejcol] =
                __float2bfloat16(hn - __bfloat162float(hhi));
            g_hs[(size_t)(bglob * Ssz + t) * Hsz + ejcol] = hn;

            __threadfence();                 // release h stores (storers only)
        }
        __syncthreads();
        // ---- per-bgroup barrier: 64 arrivals, measured-best mechanics ----
        if (tid == 0) {
            unsigned target = 64u * (unsigned)(t + 1);
            unsigned prev = atomicAdd(cnt, 1u);
            if (prev + 1u == target) {
                atomicExch(gen, (unsigned)(t + 1));
            } else {
                long long spins = 0;
                while (ld_acq(gen) < (unsigned)(t + 1)) {
                    __nanosleep(64);
                    if (++spins > 100000000LL) break;
                }
            }
        }
        __syncthreads();
    }

    if (tid < 256)
        g_c[(bg * 32 + eb) * Hsz + ejcol] = cst;
}

// ---------------------------------------------------------------------------
// Launch 4: fused output head + final-state copy (h_t taken from g_hs[:,511])
// ---------------------------------------------------------------------------
__global__ void headfin_kernel(const float* __restrict__ Wfc, const float* __restrict__ bfc,
                               float* __restrict__ out) {
    const int blk = blockIdx.x;
    if (blk < 4096) {
        int warp = blk * 8 + ((int)threadIdx.x >> 5);
        int lane = threadIdx.x & 31;
        const float* hrow = &g_hs[(size_t)warp * Hsz];
        float acc = 0.0f;
        #pragma unroll
        for (int q = 0; q < 4; q++) {
            float4 h = *(const float4*)&hrow[q * 128 + lane * 4];
            float4 w = *(const float4*)&Wfc[q * 128 + lane * 4];
            acc += h.x * w.x + h.y * w.y + h.z * w.z + h.w * w.w;
        }
        #pragma unroll
        for (int s = 16; s > 0; s >>= 1) acc += __shfl_xor_sync(0xFFFFFFFFu, acc, s);
        if (lane == 0) out[warp] = acc + bfc[0];
    } else {
        int i = (blk - 4096) * 256 + threadIdx.x;
        #pragma unroll
        for (int r = 0; r < 2; r++) {
            int v = i * 2 + r;                  // 0..32767 = b*512 + j
            int b = v >> 9, j = v & 511;
            out[32768 + v] = g_hs[(size_t)(b * Ssz + 511) * Hsz + j];
            out[65536 + v] = g_c[v];
        }
    }
}

// ---------------------------------------------------------------------------
extern "C" void kernel_launch(void* const* d_in, const int* in_sizes, int n_in,
                              void* d_out, int out_size) {
    const float* x   = (const float*)d_in[0];
    const float* Wf  = (const float*)d_in[1];
    const float* Wi  = (const float*)d_in[2];
    const float* Wo  = (const float*)d_in[3];
    const float* Wc  = (const float*)d_in[4];
    const float* bf  = (const float*)d_in[5];
    const float* bi  = (const float*)d_in[6];
    const float* bo  = (const float*)d_in[7];
    const float* bc  = (const float*)d_in[8];
    const float* Uf  = (const float*)d_in[9];
    const float* Ui  = (const float*)d_in[10];
    const float* Uo  = (const float*)d_in[11];
    const float* Uc  = (const float*)d_in[12];
    const float* Wfc = (const float*)d_in[13];
    const float* bfc = (const float*)d_in[14];
    float* out = (float*)d_out;

    cudaFuncSetAttribute(recur_kernel, cudaFuncAttributeMaxDynamicSharedMemorySize, RN_SMEM);
    cudaFuncSetAttribute(gemm_tc_kernel, cudaFuncAttributeMaxDynamicSharedMemorySize, GT_SMEM);

    init_kernel<<<128, 256>>>();                                        // launch 0
    prep_kernel<<<6144, 256>>>(Wf, Wi, Wo, Wc, bf, bi, bo, bc,
                               Uf, Ui, Uo, Uc);                         // launch 1
    gemm_tc_kernel<<<dim3(GXN / 64, ROWS / 128), 256, GT_SMEM>>>(x);    // launch 2
    recur_kernel<<<NBLK, 512, RN_SMEM>>>();                             // launch 3 (profiled)
    headfin_kernel<<<4096 + 64, 256>>>(Wfc, bfc, out);                  // launch 4
}